// round 4
// baseline (speedup 1.0000x reference)
#include <cuda_runtime.h>
#include <cuda_bf16.h>
#include <cstdint>
#include <cstddef>

#define B_ 16384
#define D_ 256
#define H_ 1024

// ---------------- scratch (device globals: no allocation allowed) ----------------
__device__ float g_noise[B_ * D_];
__device__ float g_z1t[B_ * H_];
__device__ __nv_bfloat16 g_h1b[B_ * H_];
__device__ __nv_bfloat16 g_dh1b[B_ * H_];
__device__ __nv_bfloat16 g_h2b[B_ * H_];
__device__ __nv_bfloat16 g_dh2b[B_ * H_];
__device__ __nv_bfloat16 g_W1b[(D_ + 1) * H_];
__device__ __nv_bfloat16 g_W2b[H_ * H_];
__device__ __nv_bfloat16 g_W3b[H_ * D_];
__device__ float g_v[4][B_ * D_];
__device__ float g_trp[4][8][B_];
__device__ float g_xt[B_ * D_];
__device__ float g_xe[B_ * D_];
__device__ float g_ljt[B_];

// ---------------- PTX helpers ----------------
__device__ __forceinline__ uint32_t smem_u32(const void* p) {
    uint32_t a;
    asm("{ .reg .u64 t; cvta.to.shared.u64 t, %1; cvt.u32.u64 %0, t; }" : "=r"(a) : "l"(p));
    return a;
}

#define CP_ASYNC16(dst, src) \
    asm volatile("cp.async.cg.shared.global [%0], [%1], 16;" :: "r"(dst), "l"(src) : "memory")
#define CP_COMMIT() asm volatile("cp.async.commit_group;" ::: "memory")
#define CP_WAIT(n)  asm volatile("cp.async.wait_group %0;" :: "n"(n) : "memory")

#define LDSM4(r0, r1, r2, r3, a) \
    asm volatile("ldmatrix.sync.aligned.m8n8.x4.shared.b16 {%0,%1,%2,%3}, [%4];" \
        : "=r"(r0), "=r"(r1), "=r"(r2), "=r"(r3) : "r"(a))
#define LDSM2T(r0, r1, a) \
    asm volatile("ldmatrix.sync.aligned.m8n8.x2.trans.shared.b16 {%0,%1}, [%2];" \
        : "=r"(r0), "=r"(r1) : "r"(a))

#define MMA16816(d, a, b) \
    asm volatile("mma.sync.aligned.m16n8k16.row.col.f32.bf16.bf16.f32 " \
        "{%0,%1,%2,%3}, {%4,%5,%6,%7}, {%8,%9}, {%0,%1,%2,%3};" \
        : "+f"((d)[0]), "+f"((d)[1]), "+f"((d)[2]), "+f"((d)[3]) \
        : "r"((a)[0]), "r"((a)[1]), "r"((a)[2]), "r"((a)[3]), "r"((b)[0]), "r"((b)[1]))

// ---------------- tiling ----------------
// CTA: 512 threads (16 warps, 4(M) x 4(N)); tile M=128, N=128, K-chunk 32.
// Warp tile: 32(M) x 32(N), dual-stream where STREAMS==2.
// A smem rows: 32 bf16 = 64B, padded to 80B stride (conflict-free, verified R3).
// B: two 64-col sub-tiles, each 32 rows x 128B padded to 144B stride (verified R3).
#define SM_BEFF   0
#define BUF_S     29696
#define OFF_AV(b) (512 + (b) * BUF_S)
#define OFF_AT(b) (OFF_AV(b) + 10240)
#define OFF_BB(b) (OFF_AV(b) + 20480)
#define SMEM_SZ   (512 + 2 * BUF_S)

template <bool AFP32>
__device__ __forceinline__ void stage_A(uint32_t sb, int off, const void* Ap,
                                        int K, int m0, int kc, int tid)
{
    int r = tid >> 2, q = tid & 3;   // 128 rows x 4 x 16B(bf16) chunks, 512 threads
    if (AFP32) {
        const float* s = (const float*)Ap + (size_t)(m0 + r) * K + kc + q * 8;
        float4 u = *(const float4*)s;
        float4 v = *(const float4*)(s + 4);
        __nv_bfloat162 p0 = __floats2bfloat162_rn(u.x, u.y);
        __nv_bfloat162 p1 = __floats2bfloat162_rn(u.z, u.w);
        __nv_bfloat162 p2 = __floats2bfloat162_rn(v.x, v.y);
        __nv_bfloat162 p3 = __floats2bfloat162_rn(v.z, v.w);
        uint32_t d = sb + off + r * 80 + q * 16;
        asm volatile("st.shared.v4.b32 [%0], {%1,%2,%3,%4};" :: "r"(d),
            "r"(*(uint32_t*)&p0), "r"(*(uint32_t*)&p1),
            "r"(*(uint32_t*)&p2), "r"(*(uint32_t*)&p3) : "memory");
    } else {
        const __nv_bfloat16* s = (const __nv_bfloat16*)Ap + (size_t)(m0 + r) * K + kc + q * 8;
        CP_ASYNC16(sb + off + r * 80 + q * 16, s);
    }
}

__device__ __forceinline__ void stage_B(uint32_t sb, int off, const __nv_bfloat16* W,
                                        int Ntot, int n0, int kc, int tid)
{
    int r = tid >> 4, cn = tid & 15;  // 32 rows x 16 x 16B chunks (128 cols)
    int sub = cn >> 3, ci = cn & 7;
    const __nv_bfloat16* s = W + (size_t)(kc + r) * Ntot + n0 + cn * 8;
    CP_ASYNC16(sb + off + sub * 4608 + r * 144 + ci * 16, s);
}

// MODE 0: hidden layer  -> Ho=tanh(zv+beff) bf16, Do=(1-h^2)*zt bf16 (zt from acct or Z1T)
// MODE 1: output layer  -> Vo=zv+bias fp32, Xe=Xt+cEval*Vo, trace partials from Noise*zt
// MODE 2: raw GEMM      -> Ho = zv fp32 (z1t precompute)
template <int STREAMS, int MODE, bool AFP32>
__global__ void __launch_bounds__(512)
gemm_bf16(const void* __restrict__ Avp, const void* __restrict__ Atp,
          const __nv_bfloat16* __restrict__ Wb,
          const float* __restrict__ bias, const float* __restrict__ wt, float tval,
          int K, int Ntot,
          void* __restrict__ Hop, void* __restrict__ Dop,
          const float* __restrict__ Z1T,
          float* __restrict__ Trp, const float* __restrict__ Noise,
          const float* __restrict__ Xt, float* __restrict__ Xe, float cEval)
{
    extern __shared__ char smem[];
    float* beff = (float*)smem;
    const uint32_t sb = smem_u32(smem);
    const int tid = threadIdx.x;
    const int lane = tid & 31, warp = tid >> 5;
    const int m0 = blockIdx.y * 128, n0 = blockIdx.x * 128;
    const int wm = warp >> 2, wn = warp & 3;

    if (MODE != 2 && tid < 128) {
        float be = bias[n0 + tid];
        if (MODE == 0 && wt) be += tval * wt[n0 + tid];
        beff[tid] = be;
    }

    float accv[2][4][4];
    float acct[2][4][4];
#pragma unroll
    for (int mi = 0; mi < 2; mi++)
#pragma unroll
        for (int ni = 0; ni < 4; ni++)
#pragma unroll
            for (int e = 0; e < 4; e++) { accv[mi][ni][e] = 0.f; acct[mi][ni][e] = 0.f; }

    const int NC = K / 32;

    // prologue stage chunk 0
    stage_A<AFP32>(sb, OFF_AV(0), Avp, K, m0, 0, tid);
    if (STREAMS == 2) stage_A<AFP32>(sb, OFF_AT(0), Atp, K, m0, 0, tid);
    stage_B(sb, OFF_BB(0), Wb, Ntot, n0, 0, tid);
    CP_COMMIT();

    const int lrow = ((lane >> 3) & 1) * 8 + (lane & 7);   // ldmatrix x4 lane->row
    const int lk8  = (lane >> 4) * 8;                      // ldmatrix x4 lane->k-half
    const int bk   = lane & 15;                            // ldmatrix x2 lane->k row

    for (int c = 0; c < NC; c++) {
        const int b = c & 1;
        if (c + 1 < NC) {
            const int nb = (c + 1) & 1;
            stage_A<AFP32>(sb, OFF_AV(nb), Avp, K, m0, (c + 1) * 32, tid);
            if (STREAMS == 2) stage_A<AFP32>(sb, OFF_AT(nb), Atp, K, m0, (c + 1) * 32, tid);
            stage_B(sb, OFF_BB(nb), Wb, Ntot, n0, (c + 1) * 32, tid);
            CP_COMMIT();
            CP_WAIT(1);
        } else {
            CP_WAIT(0);
        }
        __syncthreads();

        const uint32_t aav = sb + OFF_AV(b) + (wm * 32 + lrow) * 80 + lk8 * 2;
        const uint32_t aat = sb + OFF_AT(b) + (wm * 32 + lrow) * 80 + lk8 * 2;
        const uint32_t ab  = sb + OFF_BB(b) + (wn >> 1) * 4608 + bk * 144 + (wn & 1) * 64;
#pragma unroll
        for (int kk = 0; kk < 2; kk++) {
            uint32_t av[2][4], at[2][4], bf[4][2];
#pragma unroll
            for (int mi = 0; mi < 2; mi++)
                LDSM4(av[mi][0], av[mi][1], av[mi][2], av[mi][3],
                      aav + mi * 1280 + kk * 32);
            if (STREAMS == 2) {
#pragma unroll
                for (int mi = 0; mi < 2; mi++)
                    LDSM4(at[mi][0], at[mi][1], at[mi][2], at[mi][3],
                          aat + mi * 1280 + kk * 32);
            }
#pragma unroll
            for (int ni = 0; ni < 4; ni++)
                LDSM2T(bf[ni][0], bf[ni][1], ab + kk * 2304 + ni * 16);
#pragma unroll
            for (int mi = 0; mi < 2; mi++)
#pragma unroll
                for (int ni = 0; ni < 4; ni++) {
                    MMA16816(accv[mi][ni], av[mi], bf[ni]);
                    if (STREAMS == 2) MMA16816(acct[mi][ni], at[mi], bf[ni]);
                }
        }
        __syncthreads();
    }

    // ---------------- epilogue ----------------
    const int g = lane >> 2, tg = lane & 3;
    float trs[2][2] = {{0.f, 0.f}, {0.f, 0.f}};
#pragma unroll
    for (int mi = 0; mi < 2; mi++)
#pragma unroll
        for (int ni = 0; ni < 4; ni++) {
            const int colp = wn * 32 + ni * 8 + 2 * tg;
            const int colg = n0 + colp;
#pragma unroll
            for (int rh = 0; rh < 2; rh++) {
                const int row = m0 + wm * 32 + mi * 16 + rh * 8 + g;
                const float z0 = accv[mi][ni][rh * 2 + 0];
                const float z1 = accv[mi][ni][rh * 2 + 1];
                if (MODE == 2) {
                    float2 o; o.x = z0; o.y = z1;
                    *(float2*)((float*)Hop + (size_t)row * Ntot + colg) = o;
                } else if (MODE == 0) {
                    const float h0 = tanhf(z0 + beff[colp]);
                    const float h1 = tanhf(z1 + beff[colp + 1]);
                    float d0, d1;
                    if (STREAMS == 2) {
                        d0 = (1.f - h0 * h0) * acct[mi][ni][rh * 2 + 0];
                        d1 = (1.f - h1 * h1) * acct[mi][ni][rh * 2 + 1];
                    } else {
                        float2 zt = *(const float2*)(Z1T + (size_t)row * Ntot + colg);
                        d0 = (1.f - h0 * h0) * zt.x;
                        d1 = (1.f - h1 * h1) * zt.y;
                    }
                    *(__nv_bfloat162*)((__nv_bfloat16*)Hop + (size_t)row * Ntot + colg) =
                        __floats2bfloat162_rn(h0, h1);
                    *(__nv_bfloat162*)((__nv_bfloat16*)Dop + (size_t)row * Ntot + colg) =
                        __floats2bfloat162_rn(d0, d1);
                } else {
                    const float v0 = z0 + beff[colp];
                    const float v1 = z1 + beff[colp + 1];
                    const size_t o = (size_t)row * 256 + colg;
                    float2 vv; vv.x = v0; vv.y = v1;
                    *(float2*)((float*)Hop + o) = vv;
                    if (cEval != 0.f) {
                        float2 x2 = *(const float2*)(Xt + o);
                        float2 e2; e2.x = x2.x + cEval * v0; e2.y = x2.y + cEval * v1;
                        *(float2*)(Xe + o) = e2;
                    }
                    float2 nz = *(const float2*)(Noise + o);
                    trs[mi][rh] += nz.x * acct[mi][ni][rh * 2 + 0]
                                 + nz.y * acct[mi][ni][rh * 2 + 1];
                }
            }
        }
    if (MODE == 1) {
#pragma unroll
        for (int mi = 0; mi < 2; mi++)
#pragma unroll
            for (int rh = 0; rh < 2; rh++) {
                float s = trs[mi][rh];
                s += __shfl_xor_sync(0xffffffffu, s, 1);
                s += __shfl_xor_sync(0xffffffffu, s, 2);
                if (tg == 0) {
                    const int row = m0 + wm * 32 + mi * 16 + rh * 8 + g;
                    Trp[(size_t)(blockIdx.x * 4 + wn) * B_ + row] = s;
                }
            }
    }
}

// ---------------- fp32 -> bf16 weight conversion ----------------
__global__ void __launch_bounds__(256)
cvt_bf16_kernel(const float* __restrict__ in, __nv_bfloat16* __restrict__ out, int n)
{
    int i = blockIdx.x * 256 + threadIdx.x;
    if (i < n) out[i] = __float2bfloat16(in[i]);
}

// ---------------- noise = sin(1000*(x@proj))*sqrt(2), plain fp32 ----------------
__global__ void __launch_bounds__(256)
noise_kernel(const float* __restrict__ X, const float* __restrict__ P)
{
    __shared__ float As[64][17];
    __shared__ float Bs[16][68];
    int bm = blockIdx.y * 64, bn = blockIdx.x * 64;
    int tx = threadIdx.x, ty = threadIdx.y;
    int tid = ty * 16 + tx;
    float acc[4][4];
#pragma unroll
    for (int i = 0; i < 4; i++)
#pragma unroll
        for (int j = 0; j < 4; j++) acc[i][j] = 0.f;

    for (int k0 = 0; k0 < D_; k0 += 16) {
        int ar = tid >> 2, ac = (tid & 3) * 4;
        float4 a4 = *(const float4*)(X + (size_t)(bm + ar) * D_ + k0 + ac);
        As[ar][ac + 0] = a4.x; As[ar][ac + 1] = a4.y; As[ar][ac + 2] = a4.z; As[ar][ac + 3] = a4.w;
        int br = tid >> 4, bc = (tid & 15) * 4;
        float4 b4 = *(const float4*)(P + (size_t)(k0 + br) * D_ + bn + bc);
        Bs[br][bc + 0] = b4.x; Bs[br][bc + 1] = b4.y; Bs[br][bc + 2] = b4.z; Bs[br][bc + 3] = b4.w;
        __syncthreads();
#pragma unroll
        for (int k = 0; k < 16; k++) {
            float a[4], b[4];
#pragma unroll
            for (int i = 0; i < 4; i++) a[i] = As[ty * 4 + i][k];
#pragma unroll
            for (int j = 0; j < 4; j++) b[j] = Bs[k][tx * 4 + j];
#pragma unroll
            for (int i = 0; i < 4; i++)
#pragma unroll
                for (int j = 0; j < 4; j++) acc[i][j] = fmaf(a[i], b[j], acc[i][j]);
        }
        __syncthreads();
    }
#pragma unroll
    for (int i = 0; i < 4; i++)
#pragma unroll
        for (int j = 0; j < 4; j++)
            g_noise[(size_t)(bm + ty * 4 + i) * D_ + bn + tx * 4 + j] =
                sinf(1000.f * acc[i][j]) * 1.41421356f;
}

// ---------------- small kernels ----------------
__global__ void init_kernel(const float* __restrict__ X)
{
    int i = blockIdx.x * blockDim.x + threadIdx.x;
    g_xt[i] = X[i];
    if (i < B_) g_ljt[i] = 0.f;
}

__global__ void combine_kernel(float c)   // c = dt/6
{
    int i = blockIdx.x * blockDim.x + threadIdx.x;
    g_xt[i] += c * (g_v[0][i] + 2.f * g_v[1][i] + 2.f * g_v[2][i] + g_v[3][i]);
    if (i < B_) {
        float t0 = 0.f, t1 = 0.f, t2 = 0.f, t3 = 0.f;
#pragma unroll
        for (int p = 0; p < 8; p++) {
            t0 += g_trp[0][p][i];
            t1 += g_trp[1][p][i];
            t2 += g_trp[2][p][i];
            t3 += g_trp[3][p][i];
        }
        g_ljt[i] += c * (t0 + 2.f * t1 + 2.f * t2 + t3);
    }
}

__global__ void final_kernel(float* __restrict__ out)
{
    int row = blockIdx.x * 8 + (threadIdx.x >> 5);
    int lane = threadIdx.x & 31;
    const float* xr = g_xt + (size_t)row * D_;
    float s = 0.f;
#pragma unroll
    for (int c = 0; c < D_; c += 32) { float v = xr[c + lane]; s += v * v; }
#pragma unroll
    for (int o = 16; o > 0; o >>= 1) s += __shfl_xor_sync(0xffffffffu, s, o);
    if (lane == 0) out[row] = -0.5f * s - 235.2482645f - g_ljt[row];
}

// ---------------- launch ----------------
extern "C" void kernel_launch(void* const* d_in, const int* in_sizes, int n_in,
                              void* d_out, int out_size)
{
    const float* x  = (const float*)d_in[0];
    const float* W1 = (const float*)d_in[1];
    const float* b1 = (const float*)d_in[2];
    const float* W2 = (const float*)d_in[3];
    const float* b2 = (const float*)d_in[4];
    const float* W3 = (const float*)d_in[5];
    const float* b3 = (const float*)d_in[6];
    const float* pj = (const float*)d_in[7];
    float* out = (float*)d_out;

    float *noise, *z1t, *vbase, *trbase, *xt, *xe;
    __nv_bfloat16 *h1b, *dh1b, *h2b, *dh2b, *w1b, *w2b, *w3b;
    cudaGetSymbolAddress((void**)&noise,  g_noise);
    cudaGetSymbolAddress((void**)&z1t,    g_z1t);
    cudaGetSymbolAddress((void**)&h1b,    g_h1b);
    cudaGetSymbolAddress((void**)&dh1b,   g_dh1b);
    cudaGetSymbolAddress((void**)&h2b,    g_h2b);
    cudaGetSymbolAddress((void**)&dh2b,   g_dh2b);
    cudaGetSymbolAddress((void**)&w1b,    g_W1b);
    cudaGetSymbolAddress((void**)&w2b,    g_W2b);
    cudaGetSymbolAddress((void**)&w3b,    g_W3b);
    cudaGetSymbolAddress((void**)&vbase,  g_v);
    cudaGetSymbolAddress((void**)&trbase, g_trp);
    cudaGetSymbolAddress((void**)&xt,     g_xt);
    cudaGetSymbolAddress((void**)&xe,     g_xe);

    cudaFuncSetAttribute(gemm_bf16<1, 0, true>,  cudaFuncAttributeMaxDynamicSharedMemorySize, SMEM_SZ);
    cudaFuncSetAttribute(gemm_bf16<2, 0, false>, cudaFuncAttributeMaxDynamicSharedMemorySize, SMEM_SZ);
    cudaFuncSetAttribute(gemm_bf16<2, 1, false>, cudaFuncAttributeMaxDynamicSharedMemorySize, SMEM_SZ);
    cudaFuncSetAttribute(gemm_bf16<1, 2, true>,  cudaFuncAttributeMaxDynamicSharedMemorySize, SMEM_SZ);

    // prep
    cvt_bf16_kernel<<<((D_ + 1) * H_ + 255) / 256, 256>>>(W1, w1b, (D_ + 1) * H_);
    cvt_bf16_kernel<<<(H_ * H_ + 255) / 256, 256>>>(W2, w2b, H_ * H_);
    cvt_bf16_kernel<<<(H_ * D_ + 255) / 256, 256>>>(W3, w3b, H_ * D_);
    noise_kernel<<<dim3(D_ / 64, B_ / 64), dim3(16, 16)>>>(x, pj);
    init_kernel<<<(B_ * D_) / 256, 256>>>(x);

    dim3 gridH(H_ / 128, B_ / 128);   // 8 x 128
    dim3 gridD(D_ / 128, B_ / 128);   // 2 x 128

    // z1t = noise @ W1[0:256]  (constant across all evaluations)
    gemm_bf16<1, 2, true><<<gridH, 512, SMEM_SZ>>>(
        noise, nullptr, w1b, nullptr, nullptr, 0.f, D_, H_,
        z1t, nullptr, nullptr, nullptr, nullptr, nullptr, nullptr, 0.f);

    const float dt = -0.1f;
    for (int k = 0; k < 10; k++) {
        float t = 1.0f + dt * (float)k;
        struct Ev { const float* xin; float tt; int slot; float c; };
        Ev evals[4] = {
            { xt, t,              0, dt * 0.5f },
            { xe, t + dt * 0.5f,  1, dt * 0.5f },
            { xe, t + dt * 0.5f,  2, dt        },
            { xe, t + dt,         3, 0.f       },
        };
        for (int d = 0; d < 4; d++) {
            gemm_bf16<1, 0, true><<<gridH, 512, SMEM_SZ>>>(
                evals[d].xin, nullptr, w1b, b1, W1 + 256 * H_, evals[d].tt, D_, H_,
                h1b, dh1b, z1t, nullptr, nullptr, nullptr, nullptr, 0.f);
            gemm_bf16<2, 0, false><<<gridH, 512, SMEM_SZ>>>(
                h1b, dh1b, w2b, b2, nullptr, 0.f, H_, H_,
                h2b, dh2b, nullptr, nullptr, nullptr, nullptr, nullptr, 0.f);
            gemm_bf16<2, 1, false><<<gridD, 512, SMEM_SZ>>>(
                h2b, dh2b, w3b, b3, nullptr, 0.f, H_, D_,
                vbase + (size_t)evals[d].slot * B_ * D_, nullptr, nullptr,
                trbase + (size_t)evals[d].slot * 8 * B_,
                noise, xt, xe, evals[d].c);
        }
        combine_kernel<<<(B_ * D_) / 256, 256>>>(dt / 6.f);
    }
    final_kernel<<<B_ / 8, 256>>>(out);
}

// round 5
// speedup vs baseline: 1.0957x; 1.0957x over previous
#include <cuda_runtime.h>
#include <cuda_bf16.h>
#include <cstdint>
#include <cstddef>

#define B_ 16384
#define D_ 256
#define H_ 1024

// ---------------- scratch (device globals: no allocation allowed) ----------------
__device__ float g_noise[B_ * D_];
__device__ float g_z1t[B_ * H_];
__device__ float g_q[B_ * H_];
__device__ __nv_bfloat16 g_h1b[B_ * H_];
__device__ __nv_bfloat16 g_dh1b[B_ * H_];
__device__ __nv_bfloat16 g_h2b[B_ * H_];
__device__ __nv_bfloat16 g_W1b[(D_ + 1) * H_];
__device__ __nv_bfloat16 g_W2b[H_ * H_];
__device__ __nv_bfloat16 g_W3b[H_ * D_];
__device__ __nv_bfloat16 g_W3Tb[D_ * H_];
__device__ float g_trp[4][32][B_];
__device__ float g_xt[B_ * D_];
__device__ float g_xe[B_ * D_];
__device__ float g_xacc[B_ * D_];
__device__ float g_ljt[B_];

// ---------------- PTX helpers ----------------
__device__ __forceinline__ uint32_t smem_u32(const void* p) {
    uint32_t a;
    asm("{ .reg .u64 t; cvta.to.shared.u64 t, %1; cvt.u32.u64 %0, t; }" : "=r"(a) : "l"(p));
    return a;
}

#define CP_ASYNC16(dst, src) \
    asm volatile("cp.async.cg.shared.global [%0], [%1], 16;" :: "r"(dst), "l"(src) : "memory")
#define CP_COMMIT() asm volatile("cp.async.commit_group;" ::: "memory")
#define CP_WAIT(n)  asm volatile("cp.async.wait_group %0;" :: "n"(n) : "memory")

#define LDSM4(r0, r1, r2, r3, a) \
    asm volatile("ldmatrix.sync.aligned.m8n8.x4.shared.b16 {%0,%1,%2,%3}, [%4];" \
        : "=r"(r0), "=r"(r1), "=r"(r2), "=r"(r3) : "r"(a))
#define LDSM2T(r0, r1, a) \
    asm volatile("ldmatrix.sync.aligned.m8n8.x2.trans.shared.b16 {%0,%1}, [%2];" \
        : "=r"(r0), "=r"(r1) : "r"(a))

#define MMA16816(d, a, b) \
    asm volatile("mma.sync.aligned.m16n8k16.row.col.f32.bf16.bf16.f32 " \
        "{%0,%1,%2,%3}, {%4,%5,%6,%7}, {%8,%9}, {%0,%1,%2,%3};" \
        : "+f"((d)[0]), "+f"((d)[1]), "+f"((d)[2]), "+f"((d)[3]) \
        : "r"((a)[0]), "r"((a)[1]), "r"((a)[2]), "r"((a)[3]), "r"((b)[0]), "r"((b)[1]))

// ---------------- tiling (R3 shape: proven 2 CTA/SM) ----------------
// CTA: 256 threads (8 warps, 4(M) x 2(N)); tile M=128, N=64, K-chunk 32. 3-stage pipeline.
// A smem rows: 32 bf16 = 64B padded to 80B stride; B rows: 64 bf16 = 128B padded to 144B.
#define BUF_S     25088
#define OFF_AV(b) (512 + (b) * BUF_S)
#define OFF_AT(b) (OFF_AV(b) + 10240)
#define OFF_BB(b) (OFF_AV(b) + 20480)
#define SMEM_SZ   (512 + 3 * BUF_S)

template <bool AFP32>
__device__ __forceinline__ void stage_A(uint32_t sb, int off, const void* Ap,
                                        int K, int m0, int kc, int tid)
{
    if (AFP32) {
        const float* A = (const float*)Ap;
#pragma unroll
        for (int i = 0; i < 2; i++) {
            int id = tid + i * 256;
            int r = id >> 2, q = id & 3;
            const float* s = A + (size_t)(m0 + r) * K + kc + q * 8;
            float4 u = *(const float4*)s;
            float4 v = *(const float4*)(s + 4);
            __nv_bfloat162 p0 = __floats2bfloat162_rn(u.x, u.y);
            __nv_bfloat162 p1 = __floats2bfloat162_rn(u.z, u.w);
            __nv_bfloat162 p2 = __floats2bfloat162_rn(v.x, v.y);
            __nv_bfloat162 p3 = __floats2bfloat162_rn(v.z, v.w);
            uint32_t d = sb + off + r * 80 + q * 16;
            asm volatile("st.shared.v4.b32 [%0], {%1,%2,%3,%4};" :: "r"(d),
                "r"(*(uint32_t*)&p0), "r"(*(uint32_t*)&p1),
                "r"(*(uint32_t*)&p2), "r"(*(uint32_t*)&p3) : "memory");
        }
    } else {
        const __nv_bfloat16* A = (const __nv_bfloat16*)Ap;
#pragma unroll
        for (int i = 0; i < 2; i++) {
            int id = tid + i * 256;
            int r = id >> 2, q = id & 3;
            CP_ASYNC16(sb + off + r * 80 + q * 16,
                       A + (size_t)(m0 + r) * K + kc + q * 8);
        }
    }
}

__device__ __forceinline__ void stage_B(uint32_t sb, int off, const __nv_bfloat16* W,
                                        int Ntot, int n0, int kc, int tid)
{
    int r = tid >> 3, cn = tid & 7;   // 32 rows x 8 x 16B chunks
    CP_ASYNC16(sb + off + r * 144 + cn * 16,
               W + (size_t)(kc + r) * Ntot + n0 + cn * 8);
}

// MODE 0: L1 hidden, single-stream + cached Z1T -> Ho=tanh(zv+beff), Do=(1-h^2)*z1t  (bf16)
// MODE 3: L2 hidden, dual-stream + trace       -> Ho=tanh(zv+beff) bf16; Trp=sum q*(1-h^2)*zt
// MODE 1: L3 value,  single-stream + RK4       -> v=zv+bias; Xe/Xacc/Xt updates per slot
// MODE 2: raw fp32 GEMM                        -> Hop = zv  (z1t / q precompute)
template <int STREAMS, int MODE, bool AFP32>
__global__ void __launch_bounds__(256, 2)
gemm_bf16(const void* __restrict__ Avp, const void* __restrict__ Atp,
          const __nv_bfloat16* __restrict__ Wb,
          const float* __restrict__ bias, const float* __restrict__ wt, float tval,
          int K, int Ntot,
          void* __restrict__ Hop, void* __restrict__ Dop,
          const float* __restrict__ Z1T,
          float* __restrict__ Trp, const float* __restrict__ Q,
          float* __restrict__ Xt, float* __restrict__ Xe, float* __restrict__ Xacc,
          float cEval, float wInt, int slot)
{
    extern __shared__ char smem[];
    float* beff = (float*)smem;
    const uint32_t sb = smem_u32(smem);
    const int tid = threadIdx.x;
    const int lane = tid & 31, warp = tid >> 5;
    const int m0 = blockIdx.y * 128, n0 = blockIdx.x * 64;
    const int wm = warp >> 1, wn = warp & 1;

    if (MODE != 2 && tid < 64) {
        float be = bias[n0 + tid];
        if (MODE == 0 && wt) be += tval * wt[n0 + tid];
        beff[tid] = be;
    }

    float accv[2][4][4];
    float acct[2][4][4];
#pragma unroll
    for (int mi = 0; mi < 2; mi++)
#pragma unroll
        for (int ni = 0; ni < 4; ni++)
#pragma unroll
            for (int e = 0; e < 4; e++) { accv[mi][ni][e] = 0.f; acct[mi][ni][e] = 0.f; }

    const int NC = K / 32;

    // prologue: stage chunks 0 and 1
    stage_A<AFP32>(sb, OFF_AV(0), Avp, K, m0, 0, tid);
    if (STREAMS == 2) stage_A<AFP32>(sb, OFF_AT(0), Atp, K, m0, 0, tid);
    stage_B(sb, OFF_BB(0), Wb, Ntot, n0, 0, tid);
    CP_COMMIT();
    stage_A<AFP32>(sb, OFF_AV(1), Avp, K, m0, 32, tid);
    if (STREAMS == 2) stage_A<AFP32>(sb, OFF_AT(1), Atp, K, m0, 32, tid);
    stage_B(sb, OFF_BB(1), Wb, Ntot, n0, 32, tid);
    CP_COMMIT();

    const int lrow = ((lane >> 3) & 1) * 8 + (lane & 7);   // ldmatrix x4 lane->row
    const int lk8  = (lane >> 4) * 8;                      // ldmatrix x4 lane->k-half
    const int bk   = lane & 15;                            // ldmatrix x2 lane->k row

    for (int c = 0; c < NC; c++) {
        const int b = c % 3;
        if (c + 2 < NC) {
            const int nb = (c + 2) % 3;
            stage_A<AFP32>(sb, OFF_AV(nb), Avp, K, m0, (c + 2) * 32, tid);
            if (STREAMS == 2) stage_A<AFP32>(sb, OFF_AT(nb), Atp, K, m0, (c + 2) * 32, tid);
            stage_B(sb, OFF_BB(nb), Wb, Ntot, n0, (c + 2) * 32, tid);
            CP_COMMIT();
            CP_WAIT(2);
        } else if (c + 1 < NC) {
            CP_WAIT(1);
        } else {
            CP_WAIT(0);
        }
        __syncthreads();

        const uint32_t aav = sb + OFF_AV(b) + (wm * 32 + lrow) * 80 + lk8 * 2;
        const uint32_t aat = sb + OFF_AT(b) + (wm * 32 + lrow) * 80 + lk8 * 2;
        const uint32_t ab  = sb + OFF_BB(b) + bk * 144 + wn * 64;
#pragma unroll
        for (int kk = 0; kk < 2; kk++) {
            uint32_t av[2][4], at[2][4], bf[4][2];
#pragma unroll
            for (int mi = 0; mi < 2; mi++)
                LDSM4(av[mi][0], av[mi][1], av[mi][2], av[mi][3],
                      aav + mi * 1280 + kk * 32);
            if (STREAMS == 2) {
#pragma unroll
                for (int mi = 0; mi < 2; mi++)
                    LDSM4(at[mi][0], at[mi][1], at[mi][2], at[mi][3],
                          aat + mi * 1280 + kk * 32);
            }
#pragma unroll
            for (int ni = 0; ni < 4; ni++)
                LDSM2T(bf[ni][0], bf[ni][1], ab + kk * 2304 + ni * 16);
#pragma unroll
            for (int mi = 0; mi < 2; mi++)
#pragma unroll
                for (int ni = 0; ni < 4; ni++) {
                    MMA16816(accv[mi][ni], av[mi], bf[ni]);
                    if (STREAMS == 2) MMA16816(acct[mi][ni], at[mi], bf[ni]);
                }
        }
        __syncthreads();
    }

    // ---------------- epilogue ----------------
    const int g = lane >> 2, tg = lane & 3;
    float trs[2][2] = {{0.f, 0.f}, {0.f, 0.f}};
#pragma unroll
    for (int mi = 0; mi < 2; mi++)
#pragma unroll
        for (int ni = 0; ni < 4; ni++) {
            const int colp = wn * 32 + ni * 8 + 2 * tg;
            const int colg = n0 + colp;
#pragma unroll
            for (int rh = 0; rh < 2; rh++) {
                const int row = m0 + wm * 32 + mi * 16 + rh * 8 + g;
                const float z0 = accv[mi][ni][rh * 2 + 0];
                const float z1 = accv[mi][ni][rh * 2 + 1];
                if (MODE == 2) {
                    float2 o; o.x = z0; o.y = z1;
                    *(float2*)((float*)Hop + (size_t)row * Ntot + colg) = o;
                } else if (MODE == 0) {
                    const float h0 = tanhf(z0 + beff[colp]);
                    const float h1 = tanhf(z1 + beff[colp + 1]);
                    float2 zt = *(const float2*)(Z1T + (size_t)row * Ntot + colg);
                    const float d0 = (1.f - h0 * h0) * zt.x;
                    const float d1 = (1.f - h1 * h1) * zt.y;
                    *(__nv_bfloat162*)((__nv_bfloat16*)Hop + (size_t)row * Ntot + colg) =
                        __floats2bfloat162_rn(h0, h1);
                    *(__nv_bfloat162*)((__nv_bfloat16*)Dop + (size_t)row * Ntot + colg) =
                        __floats2bfloat162_rn(d0, d1);
                } else if (MODE == 3) {
                    const float h0 = tanhf(z0 + beff[colp]);
                    const float h1 = tanhf(z1 + beff[colp + 1]);
                    const float d0 = (1.f - h0 * h0) * acct[mi][ni][rh * 2 + 0];
                    const float d1 = (1.f - h1 * h1) * acct[mi][ni][rh * 2 + 1];
                    *(__nv_bfloat162*)((__nv_bfloat16*)Hop + (size_t)row * Ntot + colg) =
                        __floats2bfloat162_rn(h0, h1);
                    float2 q2 = *(const float2*)(Q + (size_t)row * Ntot + colg);
                    trs[mi][rh] += q2.x * d0 + q2.y * d1;
                } else {  // MODE 1: L3 value + RK4 integration
                    const float v0 = z0 + beff[colp];
                    const float v1 = z1 + beff[colp + 1];
                    const size_t o = (size_t)row * 256 + colg;
                    if (slot == 0) {
                        float2 a2; a2.x = wInt * v0; a2.y = wInt * v1;
                        *(float2*)(Xacc + o) = a2;
                        float2 x2 = *(const float2*)(Xt + o);
                        float2 e2; e2.x = x2.x + cEval * v0; e2.y = x2.y + cEval * v1;
                        *(float2*)(Xe + o) = e2;
                    } else if (slot < 3) {
                        float2 a2 = *(const float2*)(Xacc + o);
                        a2.x += wInt * v0; a2.y += wInt * v1;
                        *(float2*)(Xacc + o) = a2;
                        float2 x2 = *(const float2*)(Xt + o);
                        float2 e2; e2.x = x2.x + cEval * v0; e2.y = x2.y + cEval * v1;
                        *(float2*)(Xe + o) = e2;
                    } else {
                        float2 a2 = *(const float2*)(Xacc + o);
                        float2 x2 = *(const float2*)(Xt + o);
                        x2.x += a2.x + wInt * v0;
                        x2.y += a2.y + wInt * v1;
                        *(float2*)(Xt + o) = x2;
                    }
                }
            }
        }
    if (MODE == 3) {
#pragma unroll
        for (int mi = 0; mi < 2; mi++)
#pragma unroll
            for (int rh = 0; rh < 2; rh++) {
                float s = trs[mi][rh];
                s += __shfl_xor_sync(0xffffffffu, s, 1);
                s += __shfl_xor_sync(0xffffffffu, s, 2);
                if (tg == 0) {
                    const int row = m0 + wm * 32 + mi * 16 + rh * 8 + g;
                    Trp[(size_t)(blockIdx.x * 2 + wn) * B_ + row] = s;
                }
            }
    }
}

// ---------------- fp32 -> bf16 weight conversion ----------------
__global__ void __launch_bounds__(256)
cvt_bf16_kernel(const float* __restrict__ in, __nv_bfloat16* __restrict__ out, int n)
{
    int i = blockIdx.x * 256 + threadIdx.x;
    if (i < n) out[i] = __float2bfloat16(in[i]);
}

// ---------------- transpose + convert: in [R][C] f32 -> out [C][R] bf16 ----------------
__global__ void __launch_bounds__(256)
transpose_cvt_kernel(const float* __restrict__ in, __nv_bfloat16* __restrict__ out,
                     int R, int C)
{
    __shared__ float t[32][33];
    int r0 = blockIdx.y * 32, c0 = blockIdx.x * 32;
    int tx = threadIdx.x, ty = threadIdx.y;
#pragma unroll
    for (int i = ty; i < 32; i += 8)
        t[i][tx] = in[(size_t)(r0 + i) * C + c0 + tx];
    __syncthreads();
#pragma unroll
    for (int i = ty; i < 32; i += 8)
        out[(size_t)(c0 + i) * R + r0 + tx] = __float2bfloat16(t[tx][i]);
}

// ---------------- noise = sin(1000*(x@proj))*sqrt(2), plain fp32 ----------------
__global__ void __launch_bounds__(256)
noise_kernel(const float* __restrict__ X, const float* __restrict__ P)
{
    __shared__ float As[64][17];
    __shared__ float Bs[16][68];
    int bm = blockIdx.y * 64, bn = blockIdx.x * 64;
    int tx = threadIdx.x, ty = threadIdx.y;
    int tid = ty * 16 + tx;
    float acc[4][4];
#pragma unroll
    for (int i = 0; i < 4; i++)
#pragma unroll
        for (int j = 0; j < 4; j++) acc[i][j] = 0.f;

    for (int k0 = 0; k0 < D_; k0 += 16) {
        int ar = tid >> 2, ac = (tid & 3) * 4;
        float4 a4 = *(const float4*)(X + (size_t)(bm + ar) * D_ + k0 + ac);
        As[ar][ac + 0] = a4.x; As[ar][ac + 1] = a4.y; As[ar][ac + 2] = a4.z; As[ar][ac + 3] = a4.w;
        int br = tid >> 4, bc = (tid & 15) * 4;
        float4 b4 = *(const float4*)(P + (size_t)(k0 + br) * D_ + bn + bc);
        Bs[br][bc + 0] = b4.x; Bs[br][bc + 1] = b4.y; Bs[br][bc + 2] = b4.z; Bs[br][bc + 3] = b4.w;
        __syncthreads();
#pragma unroll
        for (int k = 0; k < 16; k++) {
            float a[4], b[4];
#pragma unroll
            for (int i = 0; i < 4; i++) a[i] = As[ty * 4 + i][k];
#pragma unroll
            for (int j = 0; j < 4; j++) b[j] = Bs[k][tx * 4 + j];
#pragma unroll
            for (int i = 0; i < 4; i++)
#pragma unroll
                for (int j = 0; j < 4; j++) acc[i][j] = fmaf(a[i], b[j], acc[i][j]);
        }
        __syncthreads();
    }
#pragma unroll
    for (int i = 0; i < 4; i++)
#pragma unroll
        for (int j = 0; j < 4; j++)
            g_noise[(size_t)(bm + ty * 4 + i) * D_ + bn + tx * 4 + j] =
                sinf(1000.f * acc[i][j]) * 1.41421356f;
}

// ---------------- small kernels ----------------
__global__ void init_kernel(const float* __restrict__ X)
{
    int i = blockIdx.x * blockDim.x + threadIdx.x;
    g_xt[i] = X[i];
    if (i < B_) g_ljt[i] = 0.f;
}

__global__ void combine_ljt_kernel(float c)   // c = dt/6
{
    int i = blockIdx.x * blockDim.x + threadIdx.x;
    float s[4];
#pragma unroll
    for (int slot = 0; slot < 4; slot++) {
        float t = 0.f;
#pragma unroll
        for (int p = 0; p < 32; p++) t += g_trp[slot][p][i];
        s[slot] = t;
    }
    g_ljt[i] += c * (s[0] + 2.f * s[1] + 2.f * s[2] + s[3]);
}

__global__ void final_kernel(float* __restrict__ out)
{
    int row = blockIdx.x * 8 + (threadIdx.x >> 5);
    int lane = threadIdx.x & 31;
    const float* xr = g_xt + (size_t)row * D_;
    float s = 0.f;
#pragma unroll
    for (int c = 0; c < D_; c += 32) { float v = xr[c + lane]; s += v * v; }
#pragma unroll
    for (int o = 16; o > 0; o >>= 1) s += __shfl_xor_sync(0xffffffffu, s, o);
    if (lane == 0) out[row] = -0.5f * s - 235.2482645f - g_ljt[row];
}

// ---------------- launch ----------------
extern "C" void kernel_launch(void* const* d_in, const int* in_sizes, int n_in,
                              void* d_out, int out_size)
{
    const float* x  = (const float*)d_in[0];
    const float* W1 = (const float*)d_in[1];
    const float* b1 = (const float*)d_in[2];
    const float* W2 = (const float*)d_in[3];
    const float* b2 = (const float*)d_in[4];
    const float* W3 = (const float*)d_in[5];
    const float* b3 = (const float*)d_in[6];
    const float* pj = (const float*)d_in[7];
    float* out = (float*)d_out;

    float *noise, *z1t, *q, *trbase, *xt, *xe, *xacc;
    __nv_bfloat16 *h1b, *dh1b, *h2b, *w1b, *w2b, *w3b, *w3tb;
    cudaGetSymbolAddress((void**)&noise,  g_noise);
    cudaGetSymbolAddress((void**)&z1t,    g_z1t);
    cudaGetSymbolAddress((void**)&q,      g_q);
    cudaGetSymbolAddress((void**)&h1b,    g_h1b);
    cudaGetSymbolAddress((void**)&dh1b,   g_dh1b);
    cudaGetSymbolAddress((void**)&h2b,    g_h2b);
    cudaGetSymbolAddress((void**)&w1b,    g_W1b);
    cudaGetSymbolAddress((void**)&w2b,    g_W2b);
    cudaGetSymbolAddress((void**)&w3b,    g_W3b);
    cudaGetSymbolAddress((void**)&w3tb,   g_W3Tb);
    cudaGetSymbolAddress((void**)&trbase, g_trp);
    cudaGetSymbolAddress((void**)&xt,     g_xt);
    cudaGetSymbolAddress((void**)&xe,     g_xe);
    cudaGetSymbolAddress((void**)&xacc,   g_xacc);

    cudaFuncSetAttribute(gemm_bf16<1, 0, true>,  cudaFuncAttributeMaxDynamicSharedMemorySize, SMEM_SZ);
    cudaFuncSetAttribute(gemm_bf16<2, 3, false>, cudaFuncAttributeMaxDynamicSharedMemorySize, SMEM_SZ);
    cudaFuncSetAttribute(gemm_bf16<1, 1, false>, cudaFuncAttributeMaxDynamicSharedMemorySize, SMEM_SZ);
    cudaFuncSetAttribute(gemm_bf16<1, 2, true>,  cudaFuncAttributeMaxDynamicSharedMemorySize, SMEM_SZ);

    // prep
    cvt_bf16_kernel<<<((D_ + 1) * H_ + 255) / 256, 256>>>(W1, w1b, (D_ + 1) * H_);
    cvt_bf16_kernel<<<(H_ * H_ + 255) / 256, 256>>>(W2, w2b, H_ * H_);
    cvt_bf16_kernel<<<(H_ * D_ + 255) / 256, 256>>>(W3, w3b, H_ * D_);
    transpose_cvt_kernel<<<dim3(D_ / 32, H_ / 32), dim3(32, 8)>>>(W3, w3tb, H_, D_);
    noise_kernel<<<dim3(D_ / 64, B_ / 64), dim3(16, 16)>>>(x, pj);
    init_kernel<<<(B_ * D_) / 256, 256>>>(x);

    dim3 gridH(H_ / 64, B_ / 128);    // 16 x 128
    dim3 gridD(D_ / 64, B_ / 128);    // 4 x 128

    // z1t = noise @ W1[0:256]   (constant across evaluations)
    gemm_bf16<1, 2, true><<<gridH, 256, SMEM_SZ>>>(
        noise, nullptr, w1b, nullptr, nullptr, 0.f, D_, H_,
        z1t, nullptr, nullptr, nullptr, nullptr, nullptr, nullptr, nullptr, 0.f, 0.f, 0);
    // q = noise @ W3^T          (constant across evaluations)
    gemm_bf16<1, 2, true><<<gridH, 256, SMEM_SZ>>>(
        noise, nullptr, w3tb, nullptr, nullptr, 0.f, D_, H_,
        q, nullptr, nullptr, nullptr, nullptr, nullptr, nullptr, nullptr, 0.f, 0.f, 0);

    const float dt = -0.1f;
    const float w6 = dt / 6.f;
    const float wInt[4] = { w6, 2.f * w6, 2.f * w6, w6 };
    for (int k = 0; k < 10; k++) {
        float t = 1.0f + dt * (float)k;
        const float tts[4]  = { t, t + dt * 0.5f, t + dt * 0.5f, t + dt };
        const float cevs[4] = { dt * 0.5f, dt * 0.5f, dt, 0.f };
        for (int d = 0; d < 4; d++) {
            const float* xin = (d == 0) ? xt : xe;
            gemm_bf16<1, 0, true><<<gridH, 256, SMEM_SZ>>>(
                xin, nullptr, w1b, b1, W1 + 256 * H_, tts[d], D_, H_,
                h1b, dh1b, z1t, nullptr, nullptr, nullptr, nullptr, nullptr, 0.f, 0.f, 0);
            gemm_bf16<2, 3, false><<<gridH, 256, SMEM_SZ>>>(
                h1b, dh1b, w2b, b2, nullptr, 0.f, H_, H_,
                h2b, nullptr, nullptr,
                trbase + (size_t)d * 32 * B_, q, nullptr, nullptr, nullptr, 0.f, 0.f, 0);
            gemm_bf16<1, 1, false><<<gridD, 256, SMEM_SZ>>>(
                h2b, nullptr, w3b, b3, nullptr, 0.f, H_, D_,
                nullptr, nullptr, nullptr, nullptr, nullptr,
                xt, xe, xacc, cevs[d], wInt[d], d);
        }
        combine_ljt_kernel<<<B_ / 256, 256>>>(w6);
    }
    final_kernel<<<B_ / 8, 256>>>(out);
}

// round 6
// speedup vs baseline: 1.2969x; 1.1836x over previous
#include <cuda_runtime.h>
#include <cuda_bf16.h>
#include <cstdint>
#include <cstddef>

#define B_ 16384
#define D_ 256
#define H_ 1024

// ---------------- scratch (device globals: no allocation allowed) ----------------
__device__ float g_noise[B_ * D_];
__device__ float g_z1t[B_ * H_];
__device__ float g_q[B_ * H_];
__device__ __nv_bfloat16 g_h1b[B_ * H_];
__device__ __nv_bfloat16 g_dh1b[B_ * H_];
__device__ __nv_bfloat16 g_h2b[B_ * H_];
__device__ __nv_bfloat16 g_W1b[(D_ + 1) * H_];
__device__ __nv_bfloat16 g_W2b[H_ * H_];
__device__ __nv_bfloat16 g_W3b[H_ * D_];
__device__ __nv_bfloat16 g_W3Tb[D_ * H_];
__device__ float g_trp[4][32][B_];
__device__ float g_xt[B_ * D_];
__device__ float g_xe[B_ * D_];
__device__ float g_xacc[B_ * D_];
__device__ float g_ljt[B_];

// ---------------- PTX helpers ----------------
__device__ __forceinline__ uint32_t smem_u32(const void* p) {
    uint32_t a;
    asm("{ .reg .u64 t; cvta.to.shared.u64 t, %1; cvt.u32.u64 %0, t; }" : "=r"(a) : "l"(p));
    return a;
}

#define CP_ASYNC16(dst, src) \
    asm volatile("cp.async.cg.shared.global [%0], [%1], 16;" :: "r"(dst), "l"(src) : "memory")
#define CP_COMMIT() asm volatile("cp.async.commit_group;" ::: "memory")
#define CP_WAIT(n)  asm volatile("cp.async.wait_group %0;" :: "n"(n) : "memory")

#define LDSM4(r0, r1, r2, r3, a) \
    asm volatile("ldmatrix.sync.aligned.m8n8.x4.shared.b16 {%0,%1,%2,%3}, [%4];" \
        : "=r"(r0), "=r"(r1), "=r"(r2), "=r"(r3) : "r"(a))
#define LDSM4T(r0, r1, r2, r3, a) \
    asm volatile("ldmatrix.sync.aligned.m8n8.x4.trans.shared.b16 {%0,%1,%2,%3}, [%4];" \
        : "=r"(r0), "=r"(r1), "=r"(r2), "=r"(r3) : "r"(a))

#define MMA16816(d, a, b) \
    asm volatile("mma.sync.aligned.m16n8k16.row.col.f32.bf16.bf16.f32 " \
        "{%0,%1,%2,%3}, {%4,%5,%6,%7}, {%8,%9}, {%0,%1,%2,%3};" \
        : "+f"((d)[0]), "+f"((d)[1]), "+f"((d)[2]), "+f"((d)[3]) \
        : "r"((a)[0]), "r"((a)[1]), "r"((a)[2]), "r"((a)[3]), "r"((b)[0]), "r"((b)[1]))

// ---------------- tiling ----------------
// CTA: 256 threads (8 warps, 4(M) x 2(N)); tile M=128, N=64, K-chunk 64. 2-stage pipeline.
// A rows: 64 bf16 = 128B padded to 144B stride; B rows: 64 bf16 = 128B padded to 144B.
// (stride 144 = 9 x 16B banks -> conflict-free mod-8 walk, verified in R3.)
#define BUF_S     46080
#define OFF_AV(b) (512 + (b) * BUF_S)
#define OFF_AT(b) (OFF_AV(b) + 18432)
#define OFF_BB(b) (OFF_AV(b) + 36864)
#define SMEM_SZ   (512 + 2 * BUF_S)

template <bool AFP32>
__device__ __forceinline__ void stage_A(uint32_t sb, int off, const void* Ap,
                                        int K, int m0, int kc, int tid)
{
    if (AFP32) {
        const float* A = (const float*)Ap;
#pragma unroll
        for (int i = 0; i < 4; i++) {
            int id = tid + i * 256;
            int r = id >> 3, q = id & 7;
            const float* s = A + (size_t)(m0 + r) * K + kc + q * 8;
            float4 u = *(const float4*)s;
            float4 v = *(const float4*)(s + 4);
            __nv_bfloat162 p0 = __floats2bfloat162_rn(u.x, u.y);
            __nv_bfloat162 p1 = __floats2bfloat162_rn(u.z, u.w);
            __nv_bfloat162 p2 = __floats2bfloat162_rn(v.x, v.y);
            __nv_bfloat162 p3 = __floats2bfloat162_rn(v.z, v.w);
            uint32_t d = sb + off + r * 144 + q * 16;
            asm volatile("st.shared.v4.b32 [%0], {%1,%2,%3,%4};" :: "r"(d),
                "r"(*(uint32_t*)&p0), "r"(*(uint32_t*)&p1),
                "r"(*(uint32_t*)&p2), "r"(*(uint32_t*)&p3) : "memory");
        }
    } else {
        const __nv_bfloat16* A = (const __nv_bfloat16*)Ap;
#pragma unroll
        for (int i = 0; i < 4; i++) {
            int id = tid + i * 256;
            int r = id >> 3, q = id & 7;
            CP_ASYNC16(sb + off + r * 144 + q * 16,
                       A + (size_t)(m0 + r) * K + kc + q * 8);
        }
    }
}

__device__ __forceinline__ void stage_B(uint32_t sb, int off, const __nv_bfloat16* W,
                                        int Ntot, int n0, int kc, int tid)
{
#pragma unroll
    for (int i = 0; i < 2; i++) {
        int id = tid + i * 256;
        int r = id >> 3, q = id & 7;   // 64 k-rows x 8 x 16B chunks
        CP_ASYNC16(sb + off + r * 144 + q * 16,
                   W + (size_t)(kc + r) * Ntot + n0 + q * 8);
    }
}

// MODE 0: L1 hidden, single-stream + cached Z1T -> Ho=tanh(zv+beff), Do=(1-h^2)*z1t  (bf16)
// MODE 3: L2 hidden, dual-stream + trace       -> Ho=tanh(zv+beff) bf16; Trp=sum q*(1-h^2)*zt
// MODE 1: L3 value,  single-stream + RK4       -> v=zv+bias; Xe/Xacc/Xt updates per slot
// MODE 2: raw fp32 GEMM                        -> Hop = zv  (z1t / q precompute)
template <int STREAMS, int MODE, bool AFP32>
__global__ void __launch_bounds__(256, 2)
gemm_bf16(const void* __restrict__ Avp, const void* __restrict__ Atp,
          const __nv_bfloat16* __restrict__ Wb,
          const float* __restrict__ bias, const float* __restrict__ wt, float tval,
          int K, int Ntot,
          void* __restrict__ Hop, void* __restrict__ Dop,
          const float* __restrict__ Z1T,
          float* __restrict__ Trp, const float* __restrict__ Q,
          float* __restrict__ Xt, float* __restrict__ Xe, float* __restrict__ Xacc,
          float cEval, float wInt, int slot)
{
    extern __shared__ char smem[];
    float* beff = (float*)smem;
    const uint32_t sb = smem_u32(smem);
    const int tid = threadIdx.x;
    const int lane = tid & 31, warp = tid >> 5;
    const int m0 = blockIdx.y * 128, n0 = blockIdx.x * 64;
    const int wm = warp >> 1, wn = warp & 1;

    if (MODE != 2 && tid < 64) {
        float be = bias[n0 + tid];
        if (MODE == 0 && wt) be += tval * wt[n0 + tid];
        beff[tid] = be;
    }

    float accv[2][4][4];
    float acct[2][4][4];
#pragma unroll
    for (int mi = 0; mi < 2; mi++)
#pragma unroll
        for (int ni = 0; ni < 4; ni++)
#pragma unroll
            for (int e = 0; e < 4; e++) { accv[mi][ni][e] = 0.f; acct[mi][ni][e] = 0.f; }

    const int NC = K / 64;

    // prologue: stage chunk 0 into buffer 0
    stage_A<AFP32>(sb, OFF_AV(0), Avp, K, m0, 0, tid);
    if (STREAMS == 2) stage_A<AFP32>(sb, OFF_AT(0), Atp, K, m0, 0, tid);
    stage_B(sb, OFF_BB(0), Wb, Ntot, n0, 0, tid);
    CP_COMMIT();

    const int lrow = ((lane >> 3) & 1) * 8 + (lane & 7);   // ldmatrix x4 lane->row
    const int lcol = (lane >> 4) << 4;                     // ldmatrix x4 lane->16B col

    for (int c = 0; c < NC; c++) {
        const int b = c & 1;
        if (c + 1 < NC) {
            const int nb = (c + 1) & 1;
            stage_A<AFP32>(sb, OFF_AV(nb), Avp, K, m0, (c + 1) * 64, tid);
            if (STREAMS == 2) stage_A<AFP32>(sb, OFF_AT(nb), Atp, K, m0, (c + 1) * 64, tid);
            stage_B(sb, OFF_BB(nb), Wb, Ntot, n0, (c + 1) * 64, tid);
            CP_COMMIT();
            CP_WAIT(1);
        } else {
            CP_WAIT(0);
        }
        __syncthreads();

        const uint32_t aav = sb + OFF_AV(b) + (wm * 32 + lrow) * 144 + lcol;
        const uint32_t aat = sb + OFF_AT(b) + (wm * 32 + lrow) * 144 + lcol;
        const uint32_t abT = sb + OFF_BB(b) + (lane & 15) * 144 + lcol + wn * 64;
#pragma unroll
        for (int kk = 0; kk < 4; kk++) {
            uint32_t av[2][4], at[2][4], bf[4][2];
#pragma unroll
            for (int mi = 0; mi < 2; mi++)
                LDSM4(av[mi][0], av[mi][1], av[mi][2], av[mi][3],
                      aav + mi * 2304 + kk * 32);
            if (STREAMS == 2) {
#pragma unroll
                for (int mi = 0; mi < 2; mi++)
                    LDSM4(at[mi][0], at[mi][1], at[mi][2], at[mi][3],
                          aat + mi * 2304 + kk * 32);
            }
#pragma unroll
            for (int p = 0; p < 2; p++)
                LDSM4T(bf[2 * p][0], bf[2 * p][1], bf[2 * p + 1][0], bf[2 * p + 1][1],
                       abT + kk * 2304 + p * 32);
#pragma unroll
            for (int mi = 0; mi < 2; mi++)
#pragma unroll
                for (int ni = 0; ni < 4; ni++) {
                    MMA16816(accv[mi][ni], av[mi], bf[ni]);
                    if (STREAMS == 2) MMA16816(acct[mi][ni], at[mi], bf[ni]);
                }
        }
        __syncthreads();
    }

    // ---------------- epilogue ----------------
    const int g = lane >> 2, tg = lane & 3;
    float trs[2][2] = {{0.f, 0.f}, {0.f, 0.f}};
#pragma unroll
    for (int mi = 0; mi < 2; mi++)
#pragma unroll
        for (int ni = 0; ni < 4; ni++) {
            const int colp = wn * 32 + ni * 8 + 2 * tg;
            const int colg = n0 + colp;
#pragma unroll
            for (int rh = 0; rh < 2; rh++) {
                const int row = m0 + wm * 32 + mi * 16 + rh * 8 + g;
                const float z0 = accv[mi][ni][rh * 2 + 0];
                const float z1 = accv[mi][ni][rh * 2 + 1];
                if (MODE == 2) {
                    float2 o; o.x = z0; o.y = z1;
                    *(float2*)((float*)Hop + (size_t)row * Ntot + colg) = o;
                } else if (MODE == 0) {
                    const float h0 = tanhf(z0 + beff[colp]);
                    const float h1 = tanhf(z1 + beff[colp + 1]);
                    float2 zt = *(const float2*)(Z1T + (size_t)row * Ntot + colg);
                    const float d0 = (1.f - h0 * h0) * zt.x;
                    const float d1 = (1.f - h1 * h1) * zt.y;
                    *(__nv_bfloat162*)((__nv_bfloat16*)Hop + (size_t)row * Ntot + colg) =
                        __floats2bfloat162_rn(h0, h1);
                    *(__nv_bfloat162*)((__nv_bfloat16*)Dop + (size_t)row * Ntot + colg) =
                        __floats2bfloat162_rn(d0, d1);
                } else if (MODE == 3) {
                    const float h0 = tanhf(z0 + beff[colp]);
                    const float h1 = tanhf(z1 + beff[colp + 1]);
                    const float d0 = (1.f - h0 * h0) * acct[mi][ni][rh * 2 + 0];
                    const float d1 = (1.f - h1 * h1) * acct[mi][ni][rh * 2 + 1];
                    *(__nv_bfloat162*)((__nv_bfloat16*)Hop + (size_t)row * Ntot + colg) =
                        __floats2bfloat162_rn(h0, h1);
                    float2 q2 = *(const float2*)(Q + (size_t)row * Ntot + colg);
                    trs[mi][rh] += q2.x * d0 + q2.y * d1;
                } else {  // MODE 1: L3 value + RK4 integration
                    const float v0 = z0 + beff[colp];
                    const float v1 = z1 + beff[colp + 1];
                    const size_t o = (size_t)row * 256 + colg;
                    if (slot == 0) {
                        float2 a2; a2.x = wInt * v0; a2.y = wInt * v1;
                        *(float2*)(Xacc + o) = a2;
                        float2 x2 = *(const float2*)(Xt + o);
                        float2 e2; e2.x = x2.x + cEval * v0; e2.y = x2.y + cEval * v1;
                        *(float2*)(Xe + o) = e2;
                    } else if (slot < 3) {
                        float2 a2 = *(const float2*)(Xacc + o);
                        a2.x += wInt * v0; a2.y += wInt * v1;
                        *(float2*)(Xacc + o) = a2;
                        float2 x2 = *(const float2*)(Xt + o);
                        float2 e2; e2.x = x2.x + cEval * v0; e2.y = x2.y + cEval * v1;
                        *(float2*)(Xe + o) = e2;
                    } else {
                        float2 a2 = *(const float2*)(Xacc + o);
                        float2 x2 = *(const float2*)(Xt + o);
                        x2.x += a2.x + wInt * v0;
                        x2.y += a2.y + wInt * v1;
                        *(float2*)(Xt + o) = x2;
                    }
                }
            }
        }
    if (MODE == 3) {
#pragma unroll
        for (int mi = 0; mi < 2; mi++)
#pragma unroll
            for (int rh = 0; rh < 2; rh++) {
                float s = trs[mi][rh];
                s += __shfl_xor_sync(0xffffffffu, s, 1);
                s += __shfl_xor_sync(0xffffffffu, s, 2);
                if (tg == 0) {
                    const int row = m0 + wm * 32 + mi * 16 + rh * 8 + g;
                    Trp[(size_t)(blockIdx.x * 2 + wn) * B_ + row] = s;
                }
            }
    }
}

// ---------------- fp32 -> bf16 weight conversion ----------------
__global__ void __launch_bounds__(256)
cvt_bf16_kernel(const float* __restrict__ in, __nv_bfloat16* __restrict__ out, int n)
{
    int i = blockIdx.x * 256 + threadIdx.x;
    if (i < n) out[i] = __float2bfloat16(in[i]);
}

// ---------------- transpose + convert: in [R][C] f32 -> out [C][R] bf16 ----------------
__global__ void __launch_bounds__(256)
transpose_cvt_kernel(const float* __restrict__ in, __nv_bfloat16* __restrict__ out,
                     int R, int C)
{
    __shared__ float t[32][33];
    int r0 = blockIdx.y * 32, c0 = blockIdx.x * 32;
    int tx = threadIdx.x, ty = threadIdx.y;
#pragma unroll
    for (int i = ty; i < 32; i += 8)
        t[i][tx] = in[(size_t)(r0 + i) * C + c0 + tx];
    __syncthreads();
#pragma unroll
    for (int i = ty; i < 32; i += 8)
        out[(size_t)(c0 + i) * R + r0 + tx] = __float2bfloat16(t[tx][i]);
}

// ---------------- noise = sin(1000*(x@proj))*sqrt(2), plain fp32 ----------------
__global__ void __launch_bounds__(256)
noise_kernel(const float* __restrict__ X, const float* __restrict__ P)
{
    __shared__ float As[64][17];
    __shared__ float Bs[16][68];
    int bm = blockIdx.y * 64, bn = blockIdx.x * 64;
    int tx = threadIdx.x, ty = threadIdx.y;
    int tid = ty * 16 + tx;
    float acc[4][4];
#pragma unroll
    for (int i = 0; i < 4; i++)
#pragma unroll
        for (int j = 0; j < 4; j++) acc[i][j] = 0.f;

    for (int k0 = 0; k0 < D_; k0 += 16) {
        int ar = tid >> 2, ac = (tid & 3) * 4;
        float4 a4 = *(const float4*)(X + (size_t)(bm + ar) * D_ + k0 + ac);
        As[ar][ac + 0] = a4.x; As[ar][ac + 1] = a4.y; As[ar][ac + 2] = a4.z; As[ar][ac + 3] = a4.w;
        int br = tid >> 4, bc = (tid & 15) * 4;
        float4 b4 = *(const float4*)(P + (size_t)(k0 + br) * D_ + bn + bc);
        Bs[br][bc + 0] = b4.x; Bs[br][bc + 1] = b4.y; Bs[br][bc + 2] = b4.z; Bs[br][bc + 3] = b4.w;
        __syncthreads();
#pragma unroll
        for (int k = 0; k < 16; k++) {
            float a[4], b[4];
#pragma unroll
            for (int i = 0; i < 4; i++) a[i] = As[ty * 4 + i][k];
#pragma unroll
            for (int j = 0; j < 4; j++) b[j] = Bs[k][tx * 4 + j];
#pragma unroll
            for (int i = 0; i < 4; i++)
#pragma unroll
                for (int j = 0; j < 4; j++) acc[i][j] = fmaf(a[i], b[j], acc[i][j]);
        }
        __syncthreads();
    }
#pragma unroll
    for (int i = 0; i < 4; i++)
#pragma unroll
        for (int j = 0; j < 4; j++)
            g_noise[(size_t)(bm + ty * 4 + i) * D_ + bn + tx * 4 + j] =
                sinf(1000.f * acc[i][j]) * 1.41421356f;
}

// ---------------- small kernels ----------------
__global__ void init_kernel(const float* __restrict__ X)
{
    int i = blockIdx.x * blockDim.x + threadIdx.x;
    g_xt[i] = X[i];
    if (i < B_) g_ljt[i] = 0.f;
}

__global__ void combine_ljt_kernel(float c)   // c = dt/6
{
    int i = blockIdx.x * blockDim.x + threadIdx.x;
    float s[4];
#pragma unroll
    for (int slot = 0; slot < 4; slot++) {
        float t = 0.f;
#pragma unroll
        for (int p = 0; p < 32; p++) t += g_trp[slot][p][i];
        s[slot] = t;
    }
    g_ljt[i] += c * (s[0] + 2.f * s[1] + 2.f * s[2] + s[3]);
}

__global__ void final_kernel(float* __restrict__ out)
{
    int row = blockIdx.x * 8 + (threadIdx.x >> 5);
    int lane = threadIdx.x & 31;
    const float* xr = g_xt + (size_t)row * D_;
    float s = 0.f;
#pragma unroll
    for (int c = 0; c < D_; c += 32) { float v = xr[c + lane]; s += v * v; }
#pragma unroll
    for (int o = 16; o > 0; o >>= 1) s += __shfl_xor_sync(0xffffffffu, s, o);
    if (lane == 0) out[row] = -0.5f * s - 235.2482645f - g_ljt[row];
}

// ---------------- launch ----------------
extern "C" void kernel_launch(void* const* d_in, const int* in_sizes, int n_in,
                              void* d_out, int out_size)
{
    const float* x  = (const float*)d_in[0];
    const float* W1 = (const float*)d_in[1];
    const float* b1 = (const float*)d_in[2];
    const float* W2 = (const float*)d_in[3];
    const float* b2 = (const float*)d_in[4];
    const float* W3 = (const float*)d_in[5];
    const float* b3 = (const float*)d_in[6];
    const float* pj = (const float*)d_in[7];
    float* out = (float*)d_out;

    float *noise, *z1t, *q, *trbase, *xt, *xe, *xacc;
    __nv_bfloat16 *h1b, *dh1b, *h2b, *w1b, *w2b, *w3b, *w3tb;
    cudaGetSymbolAddress((void**)&noise,  g_noise);
    cudaGetSymbolAddress((void**)&z1t,    g_z1t);
    cudaGetSymbolAddress((void**)&q,      g_q);
    cudaGetSymbolAddress((void**)&h1b,    g_h1b);
    cudaGetSymbolAddress((void**)&dh1b,   g_dh1b);
    cudaGetSymbolAddress((void**)&h2b,    g_h2b);
    cudaGetSymbolAddress((void**)&w1b,    g_W1b);
    cudaGetSymbolAddress((void**)&w2b,    g_W2b);
    cudaGetSymbolAddress((void**)&w3b,    g_W3b);
    cudaGetSymbolAddress((void**)&w3tb,   g_W3Tb);
    cudaGetSymbolAddress((void**)&trbase, g_trp);
    cudaGetSymbolAddress((void**)&xt,     g_xt);
    cudaGetSymbolAddress((void**)&xe,     g_xe);
    cudaGetSymbolAddress((void**)&xacc,   g_xacc);

    cudaFuncSetAttribute(gemm_bf16<1, 0, true>,  cudaFuncAttributeMaxDynamicSharedMemorySize, SMEM_SZ);
    cudaFuncSetAttribute(gemm_bf16<2, 3, false>, cudaFuncAttributeMaxDynamicSharedMemorySize, SMEM_SZ);
    cudaFuncSetAttribute(gemm_bf16<1, 1, false>, cudaFuncAttributeMaxDynamicSharedMemorySize, SMEM_SZ);
    cudaFuncSetAttribute(gemm_bf16<1, 2, true>,  cudaFuncAttributeMaxDynamicSharedMemorySize, SMEM_SZ);

    // prep
    cvt_bf16_kernel<<<((D_ + 1) * H_ + 255) / 256, 256>>>(W1, w1b, (D_ + 1) * H_);
    cvt_bf16_kernel<<<(H_ * H_ + 255) / 256, 256>>>(W2, w2b, H_ * H_);
    cvt_bf16_kernel<<<(H_ * D_ + 255) / 256, 256>>>(W3, w3b, H_ * D_);
    transpose_cvt_kernel<<<dim3(D_ / 32, H_ / 32), dim3(32, 8)>>>(W3, w3tb, H_, D_);
    noise_kernel<<<dim3(D_ / 64, B_ / 64), dim3(16, 16)>>>(x, pj);
    init_kernel<<<(B_ * D_) / 256, 256>>>(x);

    dim3 gridH(H_ / 64, B_ / 128);    // 16 x 128
    dim3 gridD(D_ / 64, B_ / 128);    // 4 x 128

    // z1t = noise @ W1[0:256]   (constant across evaluations)
    gemm_bf16<1, 2, true><<<gridH, 256, SMEM_SZ>>>(
        noise, nullptr, w1b, nullptr, nullptr, 0.f, D_, H_,
        z1t, nullptr, nullptr, nullptr, nullptr, nullptr, nullptr, nullptr, 0.f, 0.f, 0);
    // q = noise @ W3^T          (constant across evaluations)
    gemm_bf16<1, 2, true><<<gridH, 256, SMEM_SZ>>>(
        noise, nullptr, w3tb, nullptr, nullptr, 0.f, D_, H_,
        q, nullptr, nullptr, nullptr, nullptr, nullptr, nullptr, nullptr, 0.f, 0.f, 0);

    const float dt = -0.1f;
    const float w6 = dt / 6.f;
    const float wInt[4] = { w6, 2.f * w6, 2.f * w6, w6 };
    for (int k = 0; k < 10; k++) {
        float t = 1.0f + dt * (float)k;
        const float tts[4]  = { t, t + dt * 0.5f, t + dt * 0.5f, t + dt };
        const float cevs[4] = { dt * 0.5f, dt * 0.5f, dt, 0.f };
        for (int d = 0; d < 4; d++) {
            const float* xin = (d == 0) ? xt : xe;
            gemm_bf16<1, 0, true><<<gridH, 256, SMEM_SZ>>>(
                xin, nullptr, w1b, b1, W1 + 256 * H_, tts[d], D_, H_,
                h1b, dh1b, z1t, nullptr, nullptr, nullptr, nullptr, nullptr, 0.f, 0.f, 0);
            gemm_bf16<2, 3, false><<<gridH, 256, SMEM_SZ>>>(
                h1b, dh1b, w2b, b2, nullptr, 0.f, H_, H_,
                h2b, nullptr, nullptr,
                trbase + (size_t)d * 32 * B_, q, nullptr, nullptr, nullptr, 0.f, 0.f, 0);
            gemm_bf16<1, 1, false><<<gridD, 256, SMEM_SZ>>>(
                h2b, nullptr, w3b, b3, nullptr, 0.f, H_, D_,
                nullptr, nullptr, nullptr, nullptr, nullptr,
                xt, xe, xacc, cevs[d], wInt[d], d);
        }
        combine_ljt_kernel<<<B_ / 256, 256>>>(w6);
    }
    final_kernel<<<B_ / 8, 256>>>(out);
}

// round 7
// speedup vs baseline: 1.3522x; 1.0426x over previous
#include <cuda_runtime.h>
#include <cuda_bf16.h>
#include <cstdint>
#include <cstddef>

#define B_ 16384
#define D_ 256
#define H_ 1024

// ---------------- scratch (device globals: no allocation allowed) ----------------
__device__ float g_noise[B_ * D_];
__device__ float g_z1t[B_ * H_];
__device__ float g_q[B_ * H_];
__device__ __nv_bfloat16 g_h1b[B_ * H_];
__device__ __nv_bfloat16 g_dh1b[B_ * H_];
__device__ __nv_bfloat16 g_h2b[B_ * H_];
__device__ __nv_bfloat16 g_W1b[(D_ + 1) * H_];
__device__ __nv_bfloat16 g_W2b[H_ * H_];
__device__ __nv_bfloat16 g_W3b[H_ * D_];
__device__ __nv_bfloat16 g_W3Tb[D_ * H_];
__device__ float g_trp[4][32][B_];
__device__ float g_xt[B_ * D_];
__device__ __nv_bfloat16 g_xtb[B_ * D_];
__device__ __nv_bfloat16 g_xeb[B_ * D_];
__device__ float g_xacc[B_ * D_];
__device__ float g_ljt[B_];

// ---------------- PTX helpers ----------------
__device__ __forceinline__ uint32_t smem_u32(const void* p) {
    uint32_t a;
    asm("{ .reg .u64 t; cvta.to.shared.u64 t, %1; cvt.u32.u64 %0, t; }" : "=r"(a) : "l"(p));
    return a;
}

#define CP_ASYNC16(dst, src) \
    asm volatile("cp.async.cg.shared.global [%0], [%1], 16;" :: "r"(dst), "l"(src) : "memory")
#define CP_COMMIT() asm volatile("cp.async.commit_group;" ::: "memory")
#define CP_WAIT(n)  asm volatile("cp.async.wait_group %0;" :: "n"(n) : "memory")

#define LDSM4(r0, r1, r2, r3, a) \
    asm volatile("ldmatrix.sync.aligned.m8n8.x4.shared.b16 {%0,%1,%2,%3}, [%4];" \
        : "=r"(r0), "=r"(r1), "=r"(r2), "=r"(r3) : "r"(a))
#define LDSM4T(r0, r1, r2, r3, a) \
    asm volatile("ldmatrix.sync.aligned.m8n8.x4.trans.shared.b16 {%0,%1,%2,%3}, [%4];" \
        : "=r"(r0), "=r"(r1), "=r"(r2), "=r"(r3) : "r"(a))

#define MMA16816(d, a, b) \
    asm volatile("mma.sync.aligned.m16n8k16.row.col.f32.bf16.bf16.f32 " \
        "{%0,%1,%2,%3}, {%4,%5,%6,%7}, {%8,%9}, {%0,%1,%2,%3};" \
        : "+f"((d)[0]), "+f"((d)[1]), "+f"((d)[2]), "+f"((d)[3]) \
        : "r"((a)[0]), "r"((a)[1]), "r"((a)[2]), "r"((a)[3]), "r"((b)[0]), "r"((b)[1]))

// ---------------- tiling ----------------
// CTA: 256 threads (8 warps, 4(M) x 2(N)); tile M=128, N=64, K-chunk 64. 2-stage pipeline.
// A rows: 64 bf16 = 128B padded to 144B stride; B rows likewise (conflict-free mod-8 walk).
#define BUF_S     46080
#define OFF_AV(b) (512 + (b) * BUF_S)
#define OFF_AT(b) (OFF_AV(b) + 18432)
#define OFF_BB(b) (OFF_AV(b) + 36864)
#define SMEM_SZ   (512 + 2 * BUF_S)

template <bool AFP32>
__device__ __forceinline__ void stage_A(uint32_t sb, int off, const void* Ap,
                                        int K, int m0, int kc, int tid)
{
    if (AFP32) {
        const float* A = (const float*)Ap;
#pragma unroll
        for (int i = 0; i < 4; i++) {
            int id = tid + i * 256;
            int r = id >> 3, q = id & 7;
            const float* s = A + (size_t)(m0 + r) * K + kc + q * 8;
            float4 u = *(const float4*)s;
            float4 v = *(const float4*)(s + 4);
            __nv_bfloat162 p0 = __floats2bfloat162_rn(u.x, u.y);
            __nv_bfloat162 p1 = __floats2bfloat162_rn(u.z, u.w);
            __nv_bfloat162 p2 = __floats2bfloat162_rn(v.x, v.y);
            __nv_bfloat162 p3 = __floats2bfloat162_rn(v.z, v.w);
            uint32_t d = sb + off + r * 144 + q * 16;
            asm volatile("st.shared.v4.b32 [%0], {%1,%2,%3,%4};" :: "r"(d),
                "r"(*(uint32_t*)&p0), "r"(*(uint32_t*)&p1),
                "r"(*(uint32_t*)&p2), "r"(*(uint32_t*)&p3) : "memory");
        }
    } else {
        const __nv_bfloat16* A = (const __nv_bfloat16*)Ap;
#pragma unroll
        for (int i = 0; i < 4; i++) {
            int id = tid + i * 256;
            int r = id >> 3, q = id & 7;
            CP_ASYNC16(sb + off + r * 144 + q * 16,
                       A + (size_t)(m0 + r) * K + kc + q * 8);
        }
    }
}

__device__ __forceinline__ void stage_B(uint32_t sb, int off, const __nv_bfloat16* W,
                                        int Ntot, int n0, int kc, int tid)
{
#pragma unroll
    for (int i = 0; i < 2; i++) {
        int id = tid + i * 256;
        int r = id >> 3, q = id & 7;   // 64 k-rows x 8 x 16B chunks
        CP_ASYNC16(sb + off + r * 144 + q * 16,
                   W + (size_t)(kc + r) * Ntot + n0 + q * 8);
    }
}

// MODE 0: L1 hidden, single-stream + cached Z1T -> Ho=tanh(zv+beff), Do=(1-h^2)*z1t  (bf16)
// MODE 3: L2 hidden, dual-stream + trace       -> Ho=tanh(zv+beff) bf16; Trp=sum q*(1-h^2)*zt
// MODE 1: L3 value,  single-stream + RK4       -> v=zv+bias; Xeb/Xacc/Xt/ljt per slot
// MODE 2: merged z1t/q raw GEMM (blockIdx.x<16 -> Wb/Hop, else Wb2/Hop2)
template <int STREAMS, int MODE, bool AFP32>
__global__ void __launch_bounds__(256, 2)
gemm_bf16(const void* __restrict__ Avp, const void* __restrict__ Atp,
          const __nv_bfloat16* __restrict__ Wb, const __nv_bfloat16* __restrict__ Wb2,
          const float* __restrict__ bias, const float* __restrict__ wt, float tval,
          int K, int Ntot,
          void* __restrict__ Hop, void* __restrict__ Hop2, void* __restrict__ Dop,
          const float* __restrict__ Z1T,
          float* __restrict__ Trp, const float* __restrict__ Q,
          float* __restrict__ Xt, __nv_bfloat16* __restrict__ Xtb,
          __nv_bfloat16* __restrict__ Xeb, float* __restrict__ Xacc,
          float* __restrict__ Ljt, float cEval, float wInt, int slot)
{
    extern __shared__ char smem[];
    float* beff = (float*)smem;
    const uint32_t sb = smem_u32(smem);
    const int tid = threadIdx.x;
    const int lane = tid & 31, warp = tid >> 5;
    const int m0 = blockIdx.y * 128;
    const int n0 = (MODE == 2) ? (blockIdx.x & 15) * 64 : blockIdx.x * 64;
    const int wm = warp >> 1, wn = warp & 1;

    const __nv_bfloat16* Wu = (MODE == 2 && blockIdx.x >= 16) ? Wb2 : Wb;

    if (MODE != 2 && tid < 64) {
        float be = bias[n0 + tid];
        if (MODE == 0 && wt) be += tval * wt[n0 + tid];
        beff[tid] = be;
    }

    float accv[2][4][4];
    float acct[2][4][4];
#pragma unroll
    for (int mi = 0; mi < 2; mi++)
#pragma unroll
        for (int ni = 0; ni < 4; ni++)
#pragma unroll
            for (int e = 0; e < 4; e++) { accv[mi][ni][e] = 0.f; acct[mi][ni][e] = 0.f; }

    const int NC = K / 64;

    // prologue: stage chunk 0 into buffer 0
    stage_A<AFP32>(sb, OFF_AV(0), Avp, K, m0, 0, tid);
    if (STREAMS == 2) stage_A<AFP32>(sb, OFF_AT(0), Atp, K, m0, 0, tid);
    stage_B(sb, OFF_BB(0), Wu, Ntot, n0, 0, tid);
    CP_COMMIT();

    const int lrow = ((lane >> 3) & 1) * 8 + (lane & 7);   // ldmatrix x4 lane->row
    const int lcol = (lane >> 4) << 4;                     // ldmatrix x4 lane->16B col

    for (int c = 0; c < NC; c++) {
        const int b = c & 1;
        if (c + 1 < NC) {
            const int nb = (c + 1) & 1;
            stage_A<AFP32>(sb, OFF_AV(nb), Avp, K, m0, (c + 1) * 64, tid);
            if (STREAMS == 2) stage_A<AFP32>(sb, OFF_AT(nb), Atp, K, m0, (c + 1) * 64, tid);
            stage_B(sb, OFF_BB(nb), Wu, Ntot, n0, (c + 1) * 64, tid);
            CP_COMMIT();
            CP_WAIT(1);
        } else {
            CP_WAIT(0);
        }
        __syncthreads();

        const uint32_t aav = sb + OFF_AV(b) + (wm * 32 + lrow) * 144 + lcol;
        const uint32_t aat = sb + OFF_AT(b) + (wm * 32 + lrow) * 144 + lcol;
        const uint32_t abT = sb + OFF_BB(b) + (lane & 15) * 144 + lcol + wn * 64;
#pragma unroll
        for (int kk = 0; kk < 4; kk++) {
            uint32_t av[2][4], at[2][4], bf[4][2];
#pragma unroll
            for (int mi = 0; mi < 2; mi++)
                LDSM4(av[mi][0], av[mi][1], av[mi][2], av[mi][3],
                      aav + mi * 2304 + kk * 32);
            if (STREAMS == 2) {
#pragma unroll
                for (int mi = 0; mi < 2; mi++)
                    LDSM4(at[mi][0], at[mi][1], at[mi][2], at[mi][3],
                          aat + mi * 2304 + kk * 32);
            }
#pragma unroll
            for (int p = 0; p < 2; p++)
                LDSM4T(bf[2 * p][0], bf[2 * p][1], bf[2 * p + 1][0], bf[2 * p + 1][1],
                       abT + kk * 2304 + p * 32);
#pragma unroll
            for (int mi = 0; mi < 2; mi++)
#pragma unroll
                for (int ni = 0; ni < 4; ni++) {
                    MMA16816(accv[mi][ni], av[mi], bf[ni]);
                    if (STREAMS == 2) MMA16816(acct[mi][ni], at[mi], bf[ni]);
                }
        }
        __syncthreads();
    }

    // ---------------- epilogue ----------------
    const int g = lane >> 2, tg = lane & 3;
    float trs[2][2] = {{0.f, 0.f}, {0.f, 0.f}};
#pragma unroll
    for (int mi = 0; mi < 2; mi++)
#pragma unroll
        for (int ni = 0; ni < 4; ni++) {
            const int colp = wn * 32 + ni * 8 + 2 * tg;
            const int colg = n0 + colp;
#pragma unroll
            for (int rh = 0; rh < 2; rh++) {
                const int row = m0 + wm * 32 + mi * 16 + rh * 8 + g;
                const float z0 = accv[mi][ni][rh * 2 + 0];
                const float z1 = accv[mi][ni][rh * 2 + 1];
                if (MODE == 2) {
                    float* O = (blockIdx.x < 16) ? (float*)Hop : (float*)Hop2;
                    float2 o2; o2.x = z0; o2.y = z1;
                    *(float2*)(O + (size_t)row * Ntot + colg) = o2;
                } else if (MODE == 0) {
                    const float h0 = tanhf(z0 + beff[colp]);
                    const float h1 = tanhf(z1 + beff[colp + 1]);
                    float2 zt = *(const float2*)(Z1T + (size_t)row * Ntot + colg);
                    const float d0 = (1.f - h0 * h0) * zt.x;
                    const float d1 = (1.f - h1 * h1) * zt.y;
                    *(__nv_bfloat162*)((__nv_bfloat16*)Hop + (size_t)row * Ntot + colg) =
                        __floats2bfloat162_rn(h0, h1);
                    *(__nv_bfloat162*)((__nv_bfloat16*)Dop + (size_t)row * Ntot + colg) =
                        __floats2bfloat162_rn(d0, d1);
                } else if (MODE == 3) {
                    const float h0 = tanhf(z0 + beff[colp]);
                    const float h1 = tanhf(z1 + beff[colp + 1]);
                    const float d0 = (1.f - h0 * h0) * acct[mi][ni][rh * 2 + 0];
                    const float d1 = (1.f - h1 * h1) * acct[mi][ni][rh * 2 + 1];
                    *(__nv_bfloat162*)((__nv_bfloat16*)Hop + (size_t)row * Ntot + colg) =
                        __floats2bfloat162_rn(h0, h1);
                    float2 q2 = *(const float2*)(Q + (size_t)row * Ntot + colg);
                    trs[mi][rh] += q2.x * d0 + q2.y * d1;
                } else {  // MODE 1: L3 value + RK4 integration
                    const float v0 = z0 + beff[colp];
                    const float v1 = z1 + beff[colp + 1];
                    const size_t o = (size_t)row * 256 + colg;
                    if (slot == 0) {
                        float2 a2; a2.x = wInt * v0; a2.y = wInt * v1;
                        *(float2*)(Xacc + o) = a2;
                        float2 x2 = *(const float2*)(Xt + o);
                        *(__nv_bfloat162*)(Xeb + o) =
                            __floats2bfloat162_rn(x2.x + cEval * v0, x2.y + cEval * v1);
                    } else if (slot < 3) {
                        float2 a2 = *(const float2*)(Xacc + o);
                        a2.x += wInt * v0; a2.y += wInt * v1;
                        *(float2*)(Xacc + o) = a2;
                        float2 x2 = *(const float2*)(Xt + o);
                        *(__nv_bfloat162*)(Xeb + o) =
                            __floats2bfloat162_rn(x2.x + cEval * v0, x2.y + cEval * v1);
                    } else {
                        float2 a2 = *(const float2*)(Xacc + o);
                        float2 x2 = *(const float2*)(Xt + o);
                        x2.x += a2.x + wInt * v0;
                        x2.y += a2.y + wInt * v1;
                        *(float2*)(Xt + o) = x2;
                        *(__nv_bfloat162*)(Xtb + o) = __floats2bfloat162_rn(x2.x, x2.y);
                    }
                }
            }
        }
    if (MODE == 3) {
#pragma unroll
        for (int mi = 0; mi < 2; mi++)
#pragma unroll
            for (int rh = 0; rh < 2; rh++) {
                float s = trs[mi][rh];
                s += __shfl_xor_sync(0xffffffffu, s, 1);
                s += __shfl_xor_sync(0xffffffffu, s, 2);
                if (tg == 0) {
                    const int row = m0 + wm * 32 + mi * 16 + rh * 8 + g;
                    Trp[(size_t)(blockIdx.x * 2 + wn) * B_ + row] = s;
                }
            }
    }
    // fold ljt combine into L3 slot-3 (all 4 slots' trace partials are final by now)
    if (MODE == 1 && slot == 3 && blockIdx.x == 0 && tid < 128) {
        const int row = m0 + tid;
        float s[4];
#pragma unroll
        for (int si = 0; si < 4; si++) {
            float t = 0.f;
#pragma unroll
            for (int p = 0; p < 32; p++)
                t += Trp[(size_t)(si * 32 + p) * B_ + row];
            s[si] = t;
        }
        Ljt[row] += wInt * (s[0] + 2.f * s[1] + 2.f * s[2] + s[3]);
    }
}

// ---------------- one-shot prep: weight cvt + W3 transpose + state init ----------------
__global__ void __launch_bounds__(256)
prep_kernel(const float* __restrict__ x,
            const float* __restrict__ W1, const float* __restrict__ W2,
            const float* __restrict__ W3)
{
    int i = blockIdx.x * 256 + threadIdx.x;
    if (i < (D_ + 1) * H_) g_W1b[i] = __float2bfloat16(W1[i]);
    if (i < H_ * H_)       g_W2b[i] = __float2bfloat16(W2[i]);
    if (i < H_ * D_) {
        float w = W3[i];
        g_W3b[i] = __float2bfloat16(w);
        int r = i / D_, c = i % D_;
        g_W3Tb[(size_t)c * H_ + r] = __float2bfloat16(w);
    }
    if (i < B_ * D_) {
        float v = x[i];
        g_xt[i] = v;
        g_xtb[i] = __float2bfloat16(v);
    }
    if (i < B_) g_ljt[i] = 0.f;
}

// ---------------- noise = sin(1000*(x@proj))*sqrt(2), plain fp32 ----------------
__global__ void __launch_bounds__(256)
noise_kernel(const float* __restrict__ X, const float* __restrict__ P)
{
    __shared__ float As[64][17];
    __shared__ float Bs[16][68];
    int bm = blockIdx.y * 64, bn = blockIdx.x * 64;
    int tx = threadIdx.x, ty = threadIdx.y;
    int tid = ty * 16 + tx;
    float acc[4][4];
#pragma unroll
    for (int i = 0; i < 4; i++)
#pragma unroll
        for (int j = 0; j < 4; j++) acc[i][j] = 0.f;

    for (int k0 = 0; k0 < D_; k0 += 16) {
        int ar = tid >> 2, ac = (tid & 3) * 4;
        float4 a4 = *(const float4*)(X + (size_t)(bm + ar) * D_ + k0 + ac);
        As[ar][ac + 0] = a4.x; As[ar][ac + 1] = a4.y; As[ar][ac + 2] = a4.z; As[ar][ac + 3] = a4.w;
        int br = tid >> 4, bc = (tid & 15) * 4;
        float4 b4 = *(const float4*)(P + (size_t)(k0 + br) * D_ + bn + bc);
        Bs[br][bc + 0] = b4.x; Bs[br][bc + 1] = b4.y; Bs[br][bc + 2] = b4.z; Bs[br][bc + 3] = b4.w;
        __syncthreads();
#pragma unroll
        for (int k = 0; k < 16; k++) {
            float a[4], b[4];
#pragma unroll
            for (int i = 0; i < 4; i++) a[i] = As[ty * 4 + i][k];
#pragma unroll
            for (int j = 0; j < 4; j++) b[j] = Bs[k][tx * 4 + j];
#pragma unroll
            for (int i = 0; i < 4; i++)
#pragma unroll
                for (int j = 0; j < 4; j++) acc[i][j] = fmaf(a[i], b[j], acc[i][j]);
        }
        __syncthreads();
    }
#pragma unroll
    for (int i = 0; i < 4; i++)
#pragma unroll
        for (int j = 0; j < 4; j++)
            g_noise[(size_t)(bm + ty * 4 + i) * D_ + bn + tx * 4 + j] =
                sinf(1000.f * acc[i][j]) * 1.41421356f;
}

// ---------------- final ----------------
__global__ void final_kernel(float* __restrict__ out)
{
    int row = blockIdx.x * 8 + (threadIdx.x >> 5);
    int lane = threadIdx.x & 31;
    const float* xr = g_xt + (size_t)row * D_;
    float s = 0.f;
#pragma unroll
    for (int c = 0; c < D_; c += 32) { float v = xr[c + lane]; s += v * v; }
#pragma unroll
    for (int o = 16; o > 0; o >>= 1) s += __shfl_xor_sync(0xffffffffu, s, o);
    if (lane == 0) out[row] = -0.5f * s - 235.2482645f - g_ljt[row];
}

// ---------------- launch ----------------
extern "C" void kernel_launch(void* const* d_in, const int* in_sizes, int n_in,
                              void* d_out, int out_size)
{
    const float* x  = (const float*)d_in[0];
    const float* W1 = (const float*)d_in[1];
    const float* b1 = (const float*)d_in[2];
    const float* W2 = (const float*)d_in[3];
    const float* b2 = (const float*)d_in[4];
    const float* W3 = (const float*)d_in[5];
    const float* b3 = (const float*)d_in[6];
    const float* pj = (const float*)d_in[7];
    float* out = (float*)d_out;

    float *noise, *z1t, *q, *trbase, *xt, *xacc, *ljt;
    __nv_bfloat16 *h1b, *dh1b, *h2b, *w1b, *w2b, *w3b, *w3tb, *xtb, *xeb;
    cudaGetSymbolAddress((void**)&noise,  g_noise);
    cudaGetSymbolAddress((void**)&z1t,    g_z1t);
    cudaGetSymbolAddress((void**)&q,      g_q);
    cudaGetSymbolAddress((void**)&h1b,    g_h1b);
    cudaGetSymbolAddress((void**)&dh1b,   g_dh1b);
    cudaGetSymbolAddress((void**)&h2b,    g_h2b);
    cudaGetSymbolAddress((void**)&w1b,    g_W1b);
    cudaGetSymbolAddress((void**)&w2b,    g_W2b);
    cudaGetSymbolAddress((void**)&w3b,    g_W3b);
    cudaGetSymbolAddress((void**)&w3tb,   g_W3Tb);
    cudaGetSymbolAddress((void**)&trbase, g_trp);
    cudaGetSymbolAddress((void**)&xt,     g_xt);
    cudaGetSymbolAddress((void**)&xtb,    g_xtb);
    cudaGetSymbolAddress((void**)&xeb,    g_xeb);
    cudaGetSymbolAddress((void**)&xacc,   g_xacc);
    cudaGetSymbolAddress((void**)&ljt,    g_ljt);

    cudaFuncSetAttribute(gemm_bf16<1, 0, false>, cudaFuncAttributeMaxDynamicSharedMemorySize, SMEM_SZ);
    cudaFuncSetAttribute(gemm_bf16<2, 3, false>, cudaFuncAttributeMaxDynamicSharedMemorySize, SMEM_SZ);
    cudaFuncSetAttribute(gemm_bf16<1, 1, false>, cudaFuncAttributeMaxDynamicSharedMemorySize, SMEM_SZ);
    cudaFuncSetAttribute(gemm_bf16<1, 2, true>,  cudaFuncAttributeMaxDynamicSharedMemorySize, SMEM_SZ);

    // launch 1: merged prep
    prep_kernel<<<(B_ * D_) / 256, 256>>>(x, W1, W2, W3);
    // launch 2: noise
    noise_kernel<<<dim3(D_ / 64, B_ / 64), dim3(16, 16)>>>(x, pj);
    // launch 3: merged z1t + q  (both = noise @ {W1 slice, W3^T}, K=256)
    gemm_bf16<1, 2, true><<<dim3(32, B_ / 128), 256, SMEM_SZ>>>(
        noise, nullptr, w1b, w3tb, nullptr, nullptr, 0.f, D_, H_,
        z1t, q, nullptr, nullptr, nullptr, nullptr,
        nullptr, nullptr, nullptr, nullptr, nullptr, 0.f, 0.f, 0);

    dim3 gridH(H_ / 64, B_ / 128);    // 16 x 128
    dim3 gridD(D_ / 64, B_ / 128);    // 4 x 128

    const float dt = -0.1f;
    const float w6 = dt / 6.f;
    const float wInt[4] = { w6, 2.f * w6, 2.f * w6, w6 };
    for (int k = 0; k < 10; k++) {
        float t = 1.0f + dt * (float)k;
        const float tts[4]  = { t, t + dt * 0.5f, t + dt * 0.5f, t + dt };
        const float cevs[4] = { dt * 0.5f, dt * 0.5f, dt, 0.f };
        for (int d = 0; d < 4; d++) {
            const __nv_bfloat16* xin = (d == 0) ? xtb : xeb;
            gemm_bf16<1, 0, false><<<gridH, 256, SMEM_SZ>>>(
                xin, nullptr, w1b, nullptr, b1, W1 + 256 * H_, tts[d], D_, H_,
                h1b, nullptr, dh1b, z1t, nullptr, nullptr,
                nullptr, nullptr, nullptr, nullptr, nullptr, 0.f, 0.f, 0);
            gemm_bf16<2, 3, false><<<gridH, 256, SMEM_SZ>>>(
                h1b, dh1b, w2b, nullptr, b2, nullptr, 0.f, H_, H_,
                h2b, nullptr, nullptr, nullptr,
                trbase + (size_t)d * 32 * B_, q,
                nullptr, nullptr, nullptr, nullptr, nullptr, 0.f, 0.f, 0);
            gemm_bf16<1, 1, false><<<gridD, 256, SMEM_SZ>>>(
                h2b, nullptr, w3b, nullptr, b3, nullptr, 0.f, H_, D_,
                nullptr, nullptr, nullptr, nullptr,
                trbase, nullptr,
                xt, xtb, xeb, xacc, ljt, cevs[d], wInt[d], d);
        }
    }
    final_kernel<<<B_ / 8, 256>>>(out);
}

// round 8
// speedup vs baseline: 1.3897x; 1.0277x over previous
#include <cuda_runtime.h>
#include <cuda_bf16.h>
#include <cstdint>
#include <cstddef>

#define B_ 16384
#define D_ 256
#define H_ 1024

// ---------------- scratch (device globals: no allocation allowed) ----------------
__device__ float g_noise[B_ * D_];
__device__ __nv_bfloat16 g_z1tb[B_ * H_];
__device__ __nv_bfloat16 g_qb[B_ * H_];
__device__ __nv_bfloat16 g_h1b[B_ * H_];
__device__ __nv_bfloat16 g_dh1b[B_ * H_];
__device__ __nv_bfloat16 g_h2b[B_ * H_];
__device__ __nv_bfloat16 g_m2b[B_ * H_];
__device__ __nv_bfloat16 g_W1b[(D_ + 1) * H_];
__device__ __nv_bfloat16 g_W2b[H_ * H_];
__device__ __nv_bfloat16 g_W3b[H_ * D_];
__device__ __nv_bfloat16 g_W3Tb[D_ * H_];
__device__ float g_trp[4][16][B_];
__device__ float g_xt[B_ * D_];
__device__ __nv_bfloat16 g_xtb[B_ * D_];
__device__ __nv_bfloat16 g_xeb[B_ * D_];
__device__ float g_xacc[B_ * D_];
__device__ float g_ljt[B_];

// ---------------- PTX helpers ----------------
__device__ __forceinline__ uint32_t smem_u32(const void* p) {
    uint32_t a;
    asm("{ .reg .u64 t; cvta.to.shared.u64 t, %1; cvt.u32.u64 %0, t; }" : "=r"(a) : "l"(p));
    return a;
}

#define CP_ASYNC16(dst, src) \
    asm volatile("cp.async.cg.shared.global [%0], [%1], 16;" :: "r"(dst), "l"(src) : "memory")
#define CP_COMMIT() asm volatile("cp.async.commit_group;" ::: "memory")
#define CP_WAIT(n)  asm volatile("cp.async.wait_group %0;" :: "n"(n) : "memory")

#define LDSM4(r0, r1, r2, r3, a) \
    asm volatile("ldmatrix.sync.aligned.m8n8.x4.shared.b16 {%0,%1,%2,%3}, [%4];" \
        : "=r"(r0), "=r"(r1), "=r"(r2), "=r"(r3) : "r"(a))
#define LDSM4T(r0, r1, r2, r3, a) \
    asm volatile("ldmatrix.sync.aligned.m8n8.x4.trans.shared.b16 {%0,%1,%2,%3}, [%4];" \
        : "=r"(r0), "=r"(r1), "=r"(r2), "=r"(r3) : "r"(a))

#define MMA16816(d, a, b) \
    asm volatile("mma.sync.aligned.m16n8k16.row.col.f32.bf16.bf16.f32 " \
        "{%0,%1,%2,%3}, {%4,%5,%6,%7}, {%8,%9}, {%0,%1,%2,%3};" \
        : "+f"((d)[0]), "+f"((d)[1]), "+f"((d)[2]), "+f"((d)[3]) \
        : "r"((a)[0]), "r"((a)[1]), "r"((a)[2]), "r"((a)[3]), "r"((b)[0]), "r"((b)[1]))

// ---------------- tiling ----------------
// CTA: 256 threads (8 warps, 4(M) x 2(N)); tile M=128, N=128, K-chunk 64.
// Single-stream everywhere; warp tile 32(M) x 64(N) (64 acc regs). 2-stage pipeline.
// A rows: 64 bf16 = 128B pad to 144B (9x16B banks, conflict-free mod-8, verified R3/R6).
// B rows: 128 bf16 = 256B pad to 272B (17x16B banks, same permutation class).
#define A_BYTES   18432          // 128 rows x 144
#define B_BYTES   17408          // 64 rows x 272
#define BUF_S     (A_BYTES + B_BYTES)
#define OFF_AV(b) (512 + (b) * BUF_S)
#define OFF_BB(b) (OFF_AV(b) + A_BYTES)
#define SMEM_SZ   (512 + 2 * BUF_S)

template <bool AFP32>
__device__ __forceinline__ void stage_A(uint32_t sb, int off, const void* Ap,
                                        int K, int m0, int kc, int tid)
{
    if (AFP32) {
        const float* A = (const float*)Ap;
#pragma unroll
        for (int i = 0; i < 4; i++) {
            int id = tid + i * 256;
            int r = id >> 3, q = id & 7;
            const float* s = A + (size_t)(m0 + r) * K + kc + q * 8;
            float4 u = *(const float4*)s;
            float4 v = *(const float4*)(s + 4);
            __nv_bfloat162 p0 = __floats2bfloat162_rn(u.x, u.y);
            __nv_bfloat162 p1 = __floats2bfloat162_rn(u.z, u.w);
            __nv_bfloat162 p2 = __floats2bfloat162_rn(v.x, v.y);
            __nv_bfloat162 p3 = __floats2bfloat162_rn(v.z, v.w);
            uint32_t d = sb + off + r * 144 + q * 16;
            asm volatile("st.shared.v4.b32 [%0], {%1,%2,%3,%4};" :: "r"(d),
                "r"(*(uint32_t*)&p0), "r"(*(uint32_t*)&p1),
                "r"(*(uint32_t*)&p2), "r"(*(uint32_t*)&p3) : "memory");
        }
    } else {
        const __nv_bfloat16* A = (const __nv_bfloat16*)Ap;
#pragma unroll
        for (int i = 0; i < 4; i++) {
            int id = tid + i * 256;
            int r = id >> 3, q = id & 7;
            CP_ASYNC16(sb + off + r * 144 + q * 16,
                       A + (size_t)(m0 + r) * K + kc + q * 8);
        }
    }
}

__device__ __forceinline__ void stage_B(uint32_t sb, int off, const __nv_bfloat16* W,
                                        int Ntot, int n0, int kc, int tid)
{
#pragma unroll
    for (int i = 0; i < 4; i++) {
        int id = tid + i * 256;
        int r = id >> 4, q = id & 15;   // 64 k-rows x 16 x 16B chunks (128 cols)
        CP_ASYNC16(sb + off + r * 272 + q * 16,
                   W + (size_t)(kc + r) * Ntot + n0 + q * 8);
    }
}

// MODE 0: L1  -> Ho=tanh(z+beff) bf16, Do=(1-h^2)*z1t bf16 (z1t bf16 cached)
// MODE 4: L2v -> h2=tanh(z+beff) bf16 -> O1;  m2=(1-h2^2) bf16 -> O2
// MODE 5: L2t -> zt=z; Trp[16 partials] = sum q*m2*zt   (no bias)
// MODE 1: L3  -> v=z+bias; RK4 Xeb/Xacc/Xt + ljt fold at slot 3
// MODE 2: precompute z1t/q bf16 (blockIdx.x<8 -> Wb/O1, else Wb2/O2), A fp32
template <int MODE, bool AFP32>
__global__ void __launch_bounds__(256, 2)
gemm_bf16(const void* __restrict__ Avp,
          const __nv_bfloat16* __restrict__ Wb, const __nv_bfloat16* __restrict__ Wb2,
          const float* __restrict__ bias, const float* __restrict__ wt, float tval,
          int K, int Ntot,
          void* __restrict__ O1, void* __restrict__ O2,
          const __nv_bfloat16* __restrict__ Z1Tb,
          float* __restrict__ Trp, const __nv_bfloat16* __restrict__ Qb,
          const __nv_bfloat16* __restrict__ M2b,
          float* __restrict__ Xt, __nv_bfloat16* __restrict__ Xtb,
          __nv_bfloat16* __restrict__ Xeb, float* __restrict__ Xacc,
          float* __restrict__ Ljt, float cEval, float wInt, int slot)
{
    extern __shared__ char smem[];
    float* beff = (float*)smem;
    const uint32_t sb = smem_u32(smem);
    const int tid = threadIdx.x;
    const int lane = tid & 31, warp = tid >> 5;
    const int m0 = blockIdx.y * 128;
    const int n0 = (MODE == 2) ? (blockIdx.x & 7) * 128 : blockIdx.x * 128;
    const int wm = warp >> 1, wn = warp & 1;

    const __nv_bfloat16* Wu = (MODE == 2 && blockIdx.x >= 8) ? Wb2 : Wb;

    if (MODE != 2 && MODE != 5 && tid < 128) {
        float be = bias[n0 + tid];
        if (MODE == 0 && wt) be += tval * wt[n0 + tid];
        beff[tid] = be;
    }

    float acc[2][8][4];
#pragma unroll
    for (int mi = 0; mi < 2; mi++)
#pragma unroll
        for (int ni = 0; ni < 8; ni++)
#pragma unroll
            for (int e = 0; e < 4; e++) acc[mi][ni][e] = 0.f;

    const int NC = K / 64;

    // prologue: stage chunk 0 into buffer 0
    stage_A<AFP32>(sb, OFF_AV(0), Avp, K, m0, 0, tid);
    stage_B(sb, OFF_BB(0), Wu, Ntot, n0, 0, tid);
    CP_COMMIT();

    const int lrow = ((lane >> 3) & 1) * 8 + (lane & 7);   // ldmatrix x4 lane->row
    const int lcol = (lane >> 4) << 4;                     // ldmatrix x4 lane->16B col

    for (int c = 0; c < NC; c++) {
        const int b = c & 1;
        if (c + 1 < NC) {
            const int nb = (c + 1) & 1;
            stage_A<AFP32>(sb, OFF_AV(nb), Avp, K, m0, (c + 1) * 64, tid);
            stage_B(sb, OFF_BB(nb), Wu, Ntot, n0, (c + 1) * 64, tid);
            CP_COMMIT();
            CP_WAIT(1);
        } else {
            CP_WAIT(0);
        }
        __syncthreads();

        const uint32_t aav = sb + OFF_AV(b) + (wm * 32 + lrow) * 144 + lcol;
        const uint32_t abT = sb + OFF_BB(b) + (lane & 15) * 272 + lcol + wn * 128;
#pragma unroll
        for (int kk = 0; kk < 4; kk++) {
            uint32_t av[2][4], bf[8][2];
#pragma unroll
            for (int mi = 0; mi < 2; mi++)
                LDSM4(av[mi][0], av[mi][1], av[mi][2], av[mi][3],
                      aav + mi * 2304 + kk * 32);
#pragma unroll
            for (int p = 0; p < 4; p++)
                LDSM4T(bf[2 * p][0], bf[2 * p][1], bf[2 * p + 1][0], bf[2 * p + 1][1],
                       abT + kk * 4352 + p * 32);
#pragma unroll
            for (int mi = 0; mi < 2; mi++)
#pragma unroll
                for (int ni = 0; ni < 8; ni++)
                    MMA16816(acc[mi][ni], av[mi], bf[ni]);
        }
        __syncthreads();
    }

    // ---------------- epilogue ----------------
    const int g = lane >> 2, tg = lane & 3;
    float trs[2][2] = {{0.f, 0.f}, {0.f, 0.f}};
#pragma unroll
    for (int mi = 0; mi < 2; mi++)
#pragma unroll
        for (int ni = 0; ni < 8; ni++) {
            const int colp = wn * 64 + ni * 8 + 2 * tg;
            const int colg = n0 + colp;
#pragma unroll
            for (int rh = 0; rh < 2; rh++) {
                const int row = m0 + wm * 32 + mi * 16 + rh * 8 + g;
                const float z0 = acc[mi][ni][rh * 2 + 0];
                const float z1 = acc[mi][ni][rh * 2 + 1];
                if (MODE == 2) {
                    __nv_bfloat16* O = (blockIdx.x < 8) ? (__nv_bfloat16*)O1
                                                        : (__nv_bfloat16*)O2;
                    *(__nv_bfloat162*)(O + (size_t)row * Ntot + colg) =
                        __floats2bfloat162_rn(z0, z1);
                } else if (MODE == 0) {
                    const float h0 = tanhf(z0 + beff[colp]);
                    const float h1 = tanhf(z1 + beff[colp + 1]);
                    __nv_bfloat162 zt2 =
                        *(const __nv_bfloat162*)(Z1Tb + (size_t)row * Ntot + colg);
                    const float d0 = (1.f - h0 * h0) * __bfloat162float(zt2.x);
                    const float d1 = (1.f - h1 * h1) * __bfloat162float(zt2.y);
                    *(__nv_bfloat162*)((__nv_bfloat16*)O1 + (size_t)row * Ntot + colg) =
                        __floats2bfloat162_rn(h0, h1);
                    *(__nv_bfloat162*)((__nv_bfloat16*)O2 + (size_t)row * Ntot + colg) =
                        __floats2bfloat162_rn(d0, d1);
                } else if (MODE == 4) {
                    const float h0 = tanhf(z0 + beff[colp]);
                    const float h1 = tanhf(z1 + beff[colp + 1]);
                    *(__nv_bfloat162*)((__nv_bfloat16*)O1 + (size_t)row * Ntot + colg) =
                        __floats2bfloat162_rn(h0, h1);
                    *(__nv_bfloat162*)((__nv_bfloat16*)O2 + (size_t)row * Ntot + colg) =
                        __floats2bfloat162_rn(1.f - h0 * h0, 1.f - h1 * h1);
                } else if (MODE == 5) {
                    __nv_bfloat162 m2 =
                        *(const __nv_bfloat162*)(M2b + (size_t)row * Ntot + colg);
                    __nv_bfloat162 q2 =
                        *(const __nv_bfloat162*)(Qb + (size_t)row * Ntot + colg);
                    trs[mi][rh] += __bfloat162float(q2.x) * __bfloat162float(m2.x) * z0
                                 + __bfloat162float(q2.y) * __bfloat162float(m2.y) * z1;
                } else {  // MODE 1: L3 value + RK4 integration
                    const float v0 = z0 + beff[colp];
                    const float v1 = z1 + beff[colp + 1];
                    const size_t o = (size_t)row * 256 + colg;
                    if (slot == 0) {
                        float2 a2; a2.x = wInt * v0; a2.y = wInt * v1;
                        *(float2*)(Xacc + o) = a2;
                        float2 x2 = *(const float2*)(Xt + o);
                        *(__nv_bfloat162*)(Xeb + o) =
                            __floats2bfloat162_rn(x2.x + cEval * v0, x2.y + cEval * v1);
                    } else if (slot < 3) {
                        float2 a2 = *(const float2*)(Xacc + o);
                        a2.x += wInt * v0; a2.y += wInt * v1;
                        *(float2*)(Xacc + o) = a2;
                        float2 x2 = *(const float2*)(Xt + o);
                        *(__nv_bfloat162*)(Xeb + o) =
                            __floats2bfloat162_rn(x2.x + cEval * v0, x2.y + cEval * v1);
                    } else {
                        float2 a2 = *(const float2*)(Xacc + o);
                        float2 x2 = *(const float2*)(Xt + o);
                        x2.x += a2.x + wInt * v0;
                        x2.y += a2.y + wInt * v1;
                        *(float2*)(Xt + o) = x2;
                        *(__nv_bfloat162*)(Xtb + o) = __floats2bfloat162_rn(x2.x, x2.y);
                    }
                }
            }
        }
    if (MODE == 5) {
#pragma unroll
        for (int mi = 0; mi < 2; mi++)
#pragma unroll
            for (int rh = 0; rh < 2; rh++) {
                float s = trs[mi][rh];
                s += __shfl_xor_sync(0xffffffffu, s, 1);
                s += __shfl_xor_sync(0xffffffffu, s, 2);
                if (tg == 0) {
                    const int row = m0 + wm * 32 + mi * 16 + rh * 8 + g;
                    Trp[(size_t)(blockIdx.x * 2 + wn) * B_ + row] = s;
                }
            }
    }
    // ljt fold at L3 slot 3 (all 4 slots' trace partials final by now)
    if (MODE == 1 && slot == 3 && blockIdx.x == 0 && tid < 128) {
        const int row = m0 + tid;
        float s[4];
#pragma unroll
        for (int si = 0; si < 4; si++) {
            float t = 0.f;
#pragma unroll
            for (int p = 0; p < 16; p++)
                t += Trp[(size_t)(si * 16 + p) * B_ + row];
            s[si] = t;
        }
        Ljt[row] += wInt * (s[0] + 2.f * s[1] + 2.f * s[2] + s[3]);
    }
}

// ---------------- one-shot prep: weight cvt + W3 transpose + state init ----------------
__global__ void __launch_bounds__(256)
prep_kernel(const float* __restrict__ x,
            const float* __restrict__ W1, const float* __restrict__ W2,
            const float* __restrict__ W3)
{
    int i = blockIdx.x * 256 + threadIdx.x;
    if (i < (D_ + 1) * H_) g_W1b[i] = __float2bfloat16(W1[i]);
    if (i < H_ * H_)       g_W2b[i] = __float2bfloat16(W2[i]);
    if (i < H_ * D_) {
        float w = W3[i];
        g_W3b[i] = __float2bfloat16(w);
        int r = i / D_, c = i % D_;
        g_W3Tb[(size_t)c * H_ + r] = __float2bfloat16(w);
    }
    if (i < B_ * D_) {
        float v = x[i];
        g_xt[i] = v;
        g_xtb[i] = __float2bfloat16(v);
    }
    if (i < B_) g_ljt[i] = 0.f;
}

// ---------------- noise = sin(1000*(x@proj))*sqrt(2), plain fp32 ----------------
__global__ void __launch_bounds__(256)
noise_kernel(const float* __restrict__ X, const float* __restrict__ P)
{
    __shared__ float As[64][17];
    __shared__ float Bs[16][68];
    int bm = blockIdx.y * 64, bn = blockIdx.x * 64;
    int tx = threadIdx.x, ty = threadIdx.y;
    int tid = ty * 16 + tx;
    float acc[4][4];
#pragma unroll
    for (int i = 0; i < 4; i++)
#pragma unroll
        for (int j = 0; j < 4; j++) acc[i][j] = 0.f;

    for (int k0 = 0; k0 < D_; k0 += 16) {
        int ar = tid >> 2, ac = (tid & 3) * 4;
        float4 a4 = *(const float4*)(X + (size_t)(bm + ar) * D_ + k0 + ac);
        As[ar][ac + 0] = a4.x; As[ar][ac + 1] = a4.y; As[ar][ac + 2] = a4.z; As[ar][ac + 3] = a4.w;
        int br = tid >> 4, bc = (tid & 15) * 4;
        float4 b4 = *(const float4*)(P + (size_t)(k0 + br) * D_ + bn + bc);
        Bs[br][bc + 0] = b4.x; Bs[br][bc + 1] = b4.y; Bs[br][bc + 2] = b4.z; Bs[br][bc + 3] = b4.w;
        __syncthreads();
#pragma unroll
        for (int k = 0; k < 16; k++) {
            float a[4], b[4];
#pragma unroll
            for (int i = 0; i < 4; i++) a[i] = As[ty * 4 + i][k];
#pragma unroll
            for (int j = 0; j < 4; j++) b[j] = Bs[k][tx * 4 + j];
#pragma unroll
            for (int i = 0; i < 4; i++)
#pragma unroll
                for (int j = 0; j < 4; j++) acc[i][j] = fmaf(a[i], b[j], acc[i][j]);
        }
        __syncthreads();
    }
#pragma unroll
    for (int i = 0; i < 4; i++)
#pragma unroll
        for (int j = 0; j < 4; j++)
            g_noise[(size_t)(bm + ty * 4 + i) * D_ + bn + tx * 4 + j] =
                sinf(1000.f * acc[i][j]) * 1.41421356f;
}

// ---------------- final ----------------
__global__ void final_kernel(float* __restrict__ out)
{
    int row = blockIdx.x * 8 + (threadIdx.x >> 5);
    int lane = threadIdx.x & 31;
    const float* xr = g_xt + (size_t)row * D_;
    float s = 0.f;
#pragma unroll
    for (int c = 0; c < D_; c += 32) { float v = xr[c + lane]; s += v * v; }
#pragma unroll
    for (int o = 16; o > 0; o >>= 1) s += __shfl_xor_sync(0xffffffffu, s, o);
    if (lane == 0) out[row] = -0.5f * s - 235.2482645f - g_ljt[row];
}

// ---------------- launch ----------------
extern "C" void kernel_launch(void* const* d_in, const int* in_sizes, int n_in,
                              void* d_out, int out_size)
{
    const float* x  = (const float*)d_in[0];
    const float* W1 = (const float*)d_in[1];
    const float* b1 = (const float*)d_in[2];
    const float* W2 = (const float*)d_in[3];
    const float* b2 = (const float*)d_in[4];
    const float* W3 = (const float*)d_in[5];
    const float* b3 = (const float*)d_in[6];
    const float* pj = (const float*)d_in[7];
    float* out = (float*)d_out;

    float *noise, *trbase, *xt, *xacc, *ljt;
    __nv_bfloat16 *z1tb, *qb, *h1b, *dh1b, *h2b, *m2b, *w1b, *w2b, *w3b, *w3tb, *xtb, *xeb;
    cudaGetSymbolAddress((void**)&noise,  g_noise);
    cudaGetSymbolAddress((void**)&z1tb,   g_z1tb);
    cudaGetSymbolAddress((void**)&qb,     g_qb);
    cudaGetSymbolAddress((void**)&h1b,    g_h1b);
    cudaGetSymbolAddress((void**)&dh1b,   g_dh1b);
    cudaGetSymbolAddress((void**)&h2b,    g_h2b);
    cudaGetSymbolAddress((void**)&m2b,    g_m2b);
    cudaGetSymbolAddress((void**)&w1b,    g_W1b);
    cudaGetSymbolAddress((void**)&w2b,    g_W2b);
    cudaGetSymbolAddress((void**)&w3b,    g_W3b);
    cudaGetSymbolAddress((void**)&w3tb,   g_W3Tb);
    cudaGetSymbolAddress((void**)&trbase, g_trp);
    cudaGetSymbolAddress((void**)&xt,     g_xt);
    cudaGetSymbolAddress((void**)&xtb,    g_xtb);
    cudaGetSymbolAddress((void**)&xeb,    g_xeb);
    cudaGetSymbolAddress((void**)&xacc,   g_xacc);
    cudaGetSymbolAddress((void**)&ljt,    g_ljt);

    cudaFuncSetAttribute(gemm_bf16<0, false>, cudaFuncAttributeMaxDynamicSharedMemorySize, SMEM_SZ);
    cudaFuncSetAttribute(gemm_bf16<4, false>, cudaFuncAttributeMaxDynamicSharedMemorySize, SMEM_SZ);
    cudaFuncSetAttribute(gemm_bf16<5, false>, cudaFuncAttributeMaxDynamicSharedMemorySize, SMEM_SZ);
    cudaFuncSetAttribute(gemm_bf16<1, false>, cudaFuncAttributeMaxDynamicSharedMemorySize, SMEM_SZ);
    cudaFuncSetAttribute(gemm_bf16<2, true>,  cudaFuncAttributeMaxDynamicSharedMemorySize, SMEM_SZ);

    // launch 1: merged prep;  launch 2: noise
    prep_kernel<<<(B_ * D_) / 256, 256>>>(x, W1, W2, W3);
    noise_kernel<<<dim3(D_ / 64, B_ / 64), dim3(16, 16)>>>(x, pj);
    // launch 3: merged z1t + q (bf16 out)
    gemm_bf16<2, true><<<dim3(16, B_ / 128), 256, SMEM_SZ>>>(
        noise, w1b, w3tb, nullptr, nullptr, 0.f, D_, H_,
        z1tb, qb, nullptr, nullptr, nullptr, nullptr,
        nullptr, nullptr, nullptr, nullptr, nullptr, 0.f, 0.f, 0);

    dim3 gridH(H_ / 128, B_ / 128);   // 8 x 128
    dim3 gridD(D_ / 128, B_ / 128);   // 2 x 128 = 256 CTAs (single wave)

    const float dt = -0.1f;
    const float w6 = dt / 6.f;
    const float wInt[4] = { w6, 2.f * w6, 2.f * w6, w6 };
    for (int k = 0; k < 10; k++) {
        float t = 1.0f + dt * (float)k;
        const float tts[4]  = { t, t + dt * 0.5f, t + dt * 0.5f, t + dt };
        const float cevs[4] = { dt * 0.5f, dt * 0.5f, dt, 0.f };
        for (int d = 0; d < 4; d++) {
            const __nv_bfloat16* xin = (d == 0) ? xtb : xeb;
            // L1: h1, dh1
            gemm_bf16<0, false><<<gridH, 256, SMEM_SZ>>>(
                xin, w1b, nullptr, b1, W1 + 256 * H_, tts[d], D_, H_,
                h1b, dh1b, z1tb, nullptr, nullptr, nullptr,
                nullptr, nullptr, nullptr, nullptr, nullptr, 0.f, 0.f, 0);
            // L2 value: h2, m2
            gemm_bf16<4, false><<<gridH, 256, SMEM_SZ>>>(
                h1b, w2b, nullptr, b2, nullptr, 0.f, H_, H_,
                h2b, m2b, nullptr, nullptr, nullptr, nullptr,
                nullptr, nullptr, nullptr, nullptr, nullptr, 0.f, 0.f, 0);
            // L2 tangent: trace partials
            gemm_bf16<5, false><<<gridH, 256, SMEM_SZ>>>(
                dh1b, w2b, nullptr, nullptr, nullptr, 0.f, H_, H_,
                nullptr, nullptr, nullptr,
                trbase + (size_t)d * 16 * B_, qb, m2b,
                nullptr, nullptr, nullptr, nullptr, nullptr, 0.f, 0.f, 0);
            // L3: value + RK4 (+ ljt fold at slot 3)
            gemm_bf16<1, false><<<gridD, 256, SMEM_SZ>>>(
                h2b, w3b, nullptr, b3, nullptr, 0.f, H_, D_,
                nullptr, nullptr, nullptr,
                trbase, nullptr, nullptr,
                xt, xtb, xeb, xacc, ljt, cevs[d], wInt[d], d);
        }
    }
    final_kernel<<<B_ / 8, 256>>>(out);
}